// round 7
// baseline (speedup 1.0000x reference)
#include <cuda_runtime.h>
#include <cuda_bf16.h>
#include <cstdint>

#define B_  512
#define N_  127
#define D_  300
#define FD  1200    // 4*D : [i | o | u | f]
#define FDP 1280    // padded col stride for Z (10 tiles of 128)
#define PIOU_N 1024 // padded col count for Piou (900 used: [i|o|u] at 0/300/600)
#define PF_N   384  // padded col count for Pf (300 used)
#define AK  320     // padded K stride (10 chunks of 32)
#define WK  320

// ---------------- scratch (static device allocations) ----------------
__device__ float g_Z[(size_t)N_ * B_ * FDP];          // x @ [Wioux|Wfx] + bias
__device__ float g_Piou[(size_t)63 * B_ * PIOU_N];    // hsum @ Wiouh   (parents 0..62)
__device__ float g_Pf[(size_t)N_ * B_ * PF_N];        // h @ Wfh        (children 1..126)
__device__ float g_C[(size_t)N_ * B_ * D_];           // cell states
__device__ unsigned short g_x_hi[(size_t)N_ * B_ * AK];
__device__ unsigned short g_x_lo[(size_t)N_ * B_ * AK];
__device__ unsigned short g_h_hi[(size_t)N_ * B_ * AK];
__device__ unsigned short g_h_lo[(size_t)N_ * B_ * AK];
__device__ unsigned short g_hs_hi[(size_t)N_ * B_ * AK];   // children h-sum (parents)
__device__ unsigned short g_hs_lo[(size_t)N_ * B_ * AK];
__device__ unsigned short g_WtC_hi[FDP * WK];         // [Wioux|Wfx]^T  (n-major, k-contig)
__device__ unsigned short g_WtC_lo[FDP * WK];
__device__ unsigned short g_Wiou2_hi[PIOU_N * WK];    // Wiouh^T
__device__ unsigned short g_Wiou2_lo[PIOU_N * WK];
__device__ unsigned short g_Wfh2_hi[PF_N * WK];       // Wfh^T
__device__ unsigned short g_Wfh2_lo[PF_N * WK];
__device__ float g_bc[FDP];                           // combined bias for Z (pads zero)

__device__ __forceinline__ float sigm(float x) { return 1.0f / (1.0f + __expf(-x)); }

// ---------------- PTX helpers (sm_80-era; compile on plain sm_103) ----------------
__device__ __forceinline__ uint32_t smem_u32(const void* p) {
    uint32_t a;
    asm("{ .reg .u64 t; cvta.to.shared.u64 t, %1; cvt.u32.u64 %0, t; }" : "=r"(a) : "l"(p));
    return a;
}
__device__ __forceinline__ void cp16(uint32_t dst, const void* src) {
    uint64_t gsrc;
    asm("cvta.to.global.u64 %0, %1;" : "=l"(gsrc) : "l"(src));
    asm volatile("cp.async.cg.shared.global [%0], [%1], 16;" :: "r"(dst), "l"(gsrc));
}
#define CP_COMMIT() asm volatile("cp.async.commit_group;" ::: "memory")
#define CP_WAIT(n)  asm volatile("cp.async.wait_group %0;" :: "n"(n) : "memory")

__device__ __forceinline__ void ldsm4(uint32_t* r, uint32_t addr) {
    asm volatile("ldmatrix.sync.aligned.m8n8.x4.shared.b16 {%0,%1,%2,%3}, [%4];"
                 : "=r"(r[0]), "=r"(r[1]), "=r"(r[2]), "=r"(r[3]) : "r"(addr));
}
__device__ __forceinline__ void mma16816(float* c, const uint32_t* a, uint32_t b0, uint32_t b1) {
    asm volatile(
        "mma.sync.aligned.m16n8k16.row.col.f32.bf16.bf16.f32 "
        "{%0,%1,%2,%3}, {%4,%5,%6,%7}, {%8,%9}, {%0,%1,%2,%3};"
        : "+f"(c[0]), "+f"(c[1]), "+f"(c[2]), "+f"(c[3])
        : "r"(a[0]), "r"(a[1]), "r"(a[2]), "r"(a[3]), "r"(b0), "r"(b1));
}

// ---------------- pack weights: transpose + bf16 hi/lo split + combined bias ----------------
__global__ void pack_k(const float* __restrict__ Wioux, const float* __restrict__ bioux,
                       const float* __restrict__ Wiouh, const float* __restrict__ biouh,
                       const float* __restrict__ Wfx,  const float* __restrict__ bfx,
                       const float* __restrict__ Wfh,  const float* __restrict__ bfh) {
    int idx = blockIdx.x * blockDim.x + threadIdx.x;
    if (idx >= FDP * WK) return;
    int n = idx / WK, k = idx % WK;

    // combined x-side weights [Wioux | Wfx] (1280 rows)
    {
        float wc = 0.0f;
        if (k < D_ && n < FD) {
            wc = (n < 3 * D_) ? Wioux[k * 3 * D_ + n] : Wfx[k * D_ + n - 3 * D_];
        }
        __nv_bfloat16 h = __float2bfloat16(wc);
        g_WtC_hi[idx] = __bfloat16_as_ushort(h);
        g_WtC_lo[idx] = __bfloat16_as_ushort(__float2bfloat16(wc - __bfloat162float(h)));
    }
    // Wiouh (1024 rows)
    if (n < PIOU_N) {
        float w = (k < D_ && n < 3 * D_) ? Wiouh[k * 3 * D_ + n] : 0.0f;
        __nv_bfloat16 h = __float2bfloat16(w);
        g_Wiou2_hi[n * WK + k] = __bfloat16_as_ushort(h);
        g_Wiou2_lo[n * WK + k] = __bfloat16_as_ushort(__float2bfloat16(w - __bfloat162float(h)));
    }
    // Wfh (384 rows)
    if (n < PF_N) {
        float w = (k < D_ && n < D_) ? Wfh[k * D_ + n] : 0.0f;
        __nv_bfloat16 h = __float2bfloat16(w);
        g_Wfh2_hi[n * WK + k] = __bfloat16_as_ushort(h);
        g_Wfh2_lo[n * WK + k] = __bfloat16_as_ushort(__float2bfloat16(w - __bfloat162float(h)));
    }
    if (idx < FDP)
        g_bc[idx] = (idx >= FD) ? 0.0f
                  : (idx < 3 * D_) ? (bioux[idx] + biouh[idx])
                                   : (bfx[idx - 3 * D_] + bfh[idx - 3 * D_]);
}

// ---------------- convert x (fp32) -> bf16 hi/lo, padded K stride ----------------
__global__ void xconv_k(const float* __restrict__ x) {
    int idx = blockIdx.x * blockDim.x + threadIdx.x;
    const int pairs = AK / 2;                       // 160
    if (idx >= N_ * B_ * pairs) return;
    int r  = idx / pairs;
    int k  = (idx % pairs) * 2;
    if (k >= D_) return;                            // pads stay zero (static init)
    float a0 = x[(size_t)r * D_ + k];
    float a1 = x[(size_t)r * D_ + k + 1];
    __nv_bfloat16 h0 = __float2bfloat16(a0);
    __nv_bfloat16 h1 = __float2bfloat16(a1);
    __nv_bfloat16 l0 = __float2bfloat16(a0 - __bfloat162float(h0));
    __nv_bfloat16 l1 = __float2bfloat16(a1 - __bfloat162float(h1));
    uint32_t hh = (uint32_t)__bfloat16_as_ushort(h0) | ((uint32_t)__bfloat16_as_ushort(h1) << 16);
    uint32_t ll = (uint32_t)__bfloat16_as_ushort(l0) | ((uint32_t)__bfloat16_as_ushort(l1) << 16);
    *(uint32_t*)(g_x_hi + (size_t)r * AK + k) = hh;
    *(uint32_t*)(g_x_lo + (size_t)r * AK + k) = ll;
}

// ---------------- child h-sum for parents, split to bf16 hi/lo ----------------
__global__ void hsum_k(int pstart, int n, const float* __restrict__ hsrc) {
    int idx = blockIdx.x * blockDim.x + threadIdx.x;
    int total = n * B_ * D_;
    if (idx >= total) return;
    int d  = idx % D_;
    int rb = idx / D_;
    int b  = rb % B_;
    int j  = pstart + rb / B_;
    int a  = 2 * j + 1, a2 = 2 * j + 2;
    float s = hsrc[((size_t)b * N_ + a) * D_ + d] + hsrc[((size_t)b * N_ + a2) * D_ + d];
    __nv_bfloat16 hb = __float2bfloat16(s);
    size_t ro = (size_t)b * N_ + j;
    g_hs_hi[ro * AK + d] = __bfloat16_as_ushort(hb);
    g_hs_lo[ro * AK + d] = __bfloat16_as_ushort(__float2bfloat16(s - __bfloat162float(hb)));
}

// ---------------- mma.sync split-bf16 GEMM ----------------
// Block tile 128x128, K-tile 32, 3-stage cp.async pipeline, 8 warps (2m x 4n),
// warp tile 64x32, m16n8k16 bf16, 3-term split accumulation in fp32.
// blockIdx.x = col tile (fast; consecutive blocks share A row-block in L2),
// blockIdx.y = row tile. A row R -> node j = node_start + R/512, batch b = R%512.
// Out has col stride `ostride` covered exactly by the grid (no guards).
#define GT_THREADS 256
#define SROW 40                     // padded smem row (bf16 elems) = 80B, conflict-free
#define TILE_B (128 * SROW * 2)     // 10240 bytes per (buf) tile
#define STAGE_B (4 * TILE_B)        // Ahi,Alo,Bhi,Blo
#define SMEM_DYN (3 * STAGE_B)      // 122880

__global__ __launch_bounds__(GT_THREADS, 1) void gemm_m(
    const unsigned short* __restrict__ Ahi, const unsigned short* __restrict__ Alo,
    int node_start,
    const unsigned short* __restrict__ Bhi, const unsigned short* __restrict__ Blo,
    const float* __restrict__ bias, float* __restrict__ Out, int ostride)
{
    extern __shared__ char dsm[];
    const uint32_t sbase = smem_u32(dsm);

    const int t   = threadIdx.x;
    const int wid = t >> 5, lid = t & 31;
    const int col0 = blockIdx.x * 128;
    const int row0 = blockIdx.y * 128;
    const int wm = (wid >> 2) * 64;      // warp m offset (0/64)
    const int wn = (wid & 3) * 32;       // warp n offset (0/32/64/96)

    float acc[4][4][4];
#pragma unroll
    for (int i = 0; i < 4; i++)
#pragma unroll
        for (int j = 0; j < 4; j++)
#pragma unroll
            for (int k = 0; k < 4; k++) acc[i][j][k] = 0.0f;

    // ---- async loader for one stage ----
    auto load_stage = [&](int slot, int kt) {
        uint32_t sb = sbase + slot * STAGE_B;
        // A tiles: hi+lo, 512 16B-chunks each
#pragma unroll
        for (int i = 0; i < 4; ++i) {
            int idx = i * GT_THREADS + t;          // 0..1023
            int buf = idx >> 9;                    // 0=hi 1=lo
            int rem = idx & 511;
            int row = rem >> 2, part = rem & 3;
            int R = row0 + row;
            int j = node_start + (R >> 9);
            int b = R & (B_ - 1);
            const unsigned short* src =
                (buf ? Alo : Ahi) + ((size_t)b * N_ + j) * AK + kt + part * 8;
            cp16(sb + buf * TILE_B + row * (SROW * 2) + part * 16, src);
        }
        // B tiles: hi+lo
#pragma unroll
        for (int i = 0; i < 4; ++i) {
            int idx = i * GT_THREADS + t;
            int buf = idx >> 9;
            int rem = idx & 511;
            int row = rem >> 2, part = rem & 3;
            const unsigned short* src =
                (buf ? Blo : Bhi) + (size_t)(col0 + row) * WK + kt + part * 8;
            cp16(sb + 2 * TILE_B + buf * TILE_B + row * (SROW * 2) + part * 16, src);
        }
    };

    // ---- compute one stage ----
    const int lr = lid & 15, lc = (lid >> 4) * 8;
    auto compute_stage = [&](int slot) {
        uint32_t sA = sbase + slot * STAGE_B;
        uint32_t sB = sA + 2 * TILE_B;
#pragma unroll
        for (int ks = 0; ks < 32; ks += 16) {
            uint32_t a_hi[4][4], a_lo[4][4];
#pragma unroll
            for (int mt = 0; mt < 4; ++mt) {
                uint32_t ad = sA + ((wm + mt * 16 + lr) * SROW + ks + lc) * 2;
                ldsm4(a_hi[mt], ad);
                ldsm4(a_lo[mt], ad + TILE_B);
            }
            uint32_t b_hi[2][4], b_lo[2][4];
#pragma unroll
            for (int nh = 0; nh < 2; ++nh) {
                uint32_t bd = sB + ((wn + nh * 16 + lr) * SROW + ks + lc) * 2;
                ldsm4(b_hi[nh], bd);
                ldsm4(b_lo[nh], bd + TILE_B);
            }
#pragma unroll
            for (int mt = 0; mt < 4; ++mt)
#pragma unroll
                for (int nt = 0; nt < 4; ++nt) {
                    uint32_t bh0 = b_hi[nt >> 1][nt & 1], bh1 = b_hi[nt >> 1][(nt & 1) + 2];
                    uint32_t bl0 = b_lo[nt >> 1][nt & 1], bl1 = b_lo[nt >> 1][(nt & 1) + 2];
                    mma16816(acc[mt][nt], a_hi[mt], bh0, bh1);
                    mma16816(acc[mt][nt], a_hi[mt], bl0, bl1);
                    mma16816(acc[mt][nt], a_lo[mt], bh0, bh1);
                }
        }
    };

    // ---- pipeline: 10 K-iterations, 3 stages ----
    load_stage(0, 0);
    CP_COMMIT();
    load_stage(1, 32);
    CP_COMMIT();
#pragma unroll 1
    for (int it = 0; it < 10; ++it) {
        if (it < 9) { CP_WAIT(1); } else { CP_WAIT(0); }
        __syncthreads();
        if (it + 2 < 10) {
            load_stage((it + 2) % 3, (it + 2) * 32);
            CP_COMMIT();
        }
        compute_stage(it % 3);
    }

    // ---- epilogue ----
    const int g = lid >> 2, i4 = lid & 3;
#pragma unroll
    for (int mt = 0; mt < 4; ++mt) {
        int r0 = row0 + wm + mt * 16 + g;
#pragma unroll
        for (int nt = 0; nt < 4; ++nt) {
            int cc = col0 + wn + nt * 8 + i4 * 2;
            float b0v = 0.0f, b1v = 0.0f;
            if (bias) { b0v = bias[cc]; b1v = bias[cc + 1]; }
            float* o0 = Out + (size_t)r0 * ostride + cc;
            float* o1 = Out + (size_t)(r0 + 8) * ostride + cc;
            o0[0] = acc[mt][nt][0] + b0v;
            o0[1] = acc[mt][nt][1] + b1v;
            o1[0] = acc[mt][nt][2] + b0v;
            o1[1] = acc[mt][nt][3] + b1v;
        }
    }
}

// ---------------- leaves: c = sig(z_i)*tanh(z_u); h = sig(z_o)*tanh(c) ----------------
__global__ void leaf_k(float* __restrict__ out) {
    int idx = blockIdx.x * blockDim.x + threadIdx.x;
    const int total = 64 * B_ * D_;
    if (idx >= total) return;
    int d  = idx % D_;
    int rb = idx / D_;
    int b  = rb % B_;
    int j  = 63 + rb / B_;
    size_t zr = ((size_t)j * B_ + b) * FDP;
    float i_ = sigm(g_Z[zr + d]);
    float o_ = sigm(g_Z[zr + D_ + d]);
    float u_ = tanhf(g_Z[zr + 2 * D_ + d]);
    float c  = i_ * u_;
    g_C[((size_t)j * B_ + b) * D_ + d] = c;
    float hh = o_ * tanhf(c);
    size_t ro = (size_t)b * N_ + j;
    out[ro * D_ + d] = hh;
    __nv_bfloat16 hb = __float2bfloat16(hh);
    g_h_hi[ro * AK + d] = __bfloat16_as_ushort(hb);
    g_h_lo[ro * AK + d] = __bfloat16_as_ushort(__float2bfloat16(hh - __bfloat162float(hb)));
}

// ---------------- internal level combine ----------------
__global__ void comb_k(int start, int n, float* __restrict__ out) {
    int idx = blockIdx.x * blockDim.x + threadIdx.x;
    int total = n * B_ * D_;
    if (idx >= total) return;
    int d  = idx % D_;
    int rb = idx / D_;
    int b  = rb % B_;
    int j  = start + rb / B_;
    int a  = 2 * j + 1;
    int a2 = 2 * j + 2;
    size_t zr = ((size_t)j  * B_ + b) * FDP;
    size_t pj = ((size_t)j  * B_ + b) * PIOU_N;
    size_t pa = ((size_t)a  * B_ + b) * PF_N;
    size_t pb = ((size_t)a2 * B_ + b) * PF_N;

    float ii = sigm (g_Z[zr + d]          + g_Piou[pj + d]);
    float oo = sigm (g_Z[zr + D_ + d]     + g_Piou[pj + D_ + d]);
    float uu = tanhf(g_Z[zr + 2*D_ + d]   + g_Piou[pj + 2*D_ + d]);
    float zf = g_Z[zr + 3 * D_ + d];
    float fa = sigm(g_Pf[pa + d] + zf);
    float fb = sigm(g_Pf[pb + d] + zf);

    float ca = g_C[((size_t)a  * B_ + b) * D_ + d];
    float cb = g_C[((size_t)a2 * B_ + b) * D_ + d];
    float cc = ii * uu + fa * ca + fb * cb;
    g_C[((size_t)j * B_ + b) * D_ + d] = cc;
    float hh = oo * tanhf(cc);
    size_t ro = (size_t)b * N_ + j;
    out[ro * D_ + d] = hh;
    __nv_bfloat16 hb = __float2bfloat16(hh);
    g_h_hi[ro * AK + d] = __bfloat16_as_ushort(hb);
    g_h_lo[ro * AK + d] = __bfloat16_as_ushort(__float2bfloat16(hh - __bfloat162float(hb)));
}

extern "C" void kernel_launch(void* const* d_in, const int* in_sizes, int n_in,
                              void* d_out, int out_size) {
    const float* x     = (const float*)d_in[0];
    const float* Wioux = (const float*)d_in[1];
    const float* bioux = (const float*)d_in[2];
    const float* Wiouh = (const float*)d_in[3];
    const float* biouh = (const float*)d_in[4];
    const float* Wfx   = (const float*)d_in[5];
    const float* bfx   = (const float*)d_in[6];
    const float* Wfh   = (const float*)d_in[7];
    const float* bfh   = (const float*)d_in[8];
    float* out = (float*)d_out;

    float *Zp, *Piou, *Pf, *bcp;
    unsigned short *xh, *xl, *hh, *hl, *hsh, *hsl, *wch, *wcl, *wi2h, *wi2l, *wfh2h, *wfh2l;
    cudaGetSymbolAddress((void**)&Zp,    g_Z);
    cudaGetSymbolAddress((void**)&Piou,  g_Piou);
    cudaGetSymbolAddress((void**)&Pf,    g_Pf);
    cudaGetSymbolAddress((void**)&bcp,   g_bc);
    cudaGetSymbolAddress((void**)&xh,    g_x_hi);
    cudaGetSymbolAddress((void**)&xl,    g_x_lo);
    cudaGetSymbolAddress((void**)&hh,    g_h_hi);
    cudaGetSymbolAddress((void**)&hl,    g_h_lo);
    cudaGetSymbolAddress((void**)&hsh,   g_hs_hi);
    cudaGetSymbolAddress((void**)&hsl,   g_hs_lo);
    cudaGetSymbolAddress((void**)&wch,   g_WtC_hi);
    cudaGetSymbolAddress((void**)&wcl,   g_WtC_lo);
    cudaGetSymbolAddress((void**)&wi2h,  g_Wiou2_hi);
    cudaGetSymbolAddress((void**)&wi2l,  g_Wiou2_lo);
    cudaGetSymbolAddress((void**)&wfh2h, g_Wfh2_hi);
    cudaGetSymbolAddress((void**)&wfh2l, g_Wfh2_lo);

    cudaFuncSetAttribute(gemm_m, cudaFuncAttributeMaxDynamicSharedMemorySize, SMEM_DYN);

    // 1. pack weights (transpose + split) + combined bias
    pack_k<<<(FDP * WK + 255) / 256, 256>>>(Wioux, bioux, Wiouh, biouh, Wfx, bfx, Wfh, bfh);

    // 2. split x into bf16 hi/lo
    xconv_k<<<(N_ * B_ * (AK / 2) + 255) / 256, 256>>>(x);

    // 3. Z = x @ [Wioux|Wfx] + bias, all nodes  (M = 65024, N = 1280)
    {
        dim3 grid(FDP / 128, (N_ * B_) / 128);
        gemm_m<<<grid, GT_THREADS, SMEM_DYN>>>(xh, xl, 0, wch, wcl, bcp, Zp, FDP);
    }

    // 4. leaves (nodes 63..126)
    leaf_k<<<(64 * B_ * D_ + 255) / 256, 256>>>(out);

    // 5. levels: parents pl = 5 .. 0 (children at pl+1 already have h)
    for (int pl = 5; pl >= 0; --pl) {
        int ps = (1 << pl) - 1, np = 1 << pl;             // parent start/count
        int cs = (1 << (pl + 1)) - 1, nc = 1 << (pl + 1); // child start/count

        hsum_k<<<(np * B_ * D_ + 255) / 256, 256>>>(ps, np, out);

        // Piou[parents] = hsum @ Wiouh   (M = np*512, N = 1024)
        {
            dim3 grid(PIOU_N / 128, np * 4);
            gemm_m<<<grid, GT_THREADS, SMEM_DYN>>>(hsh, hsl, ps, wi2h, wi2l, nullptr,
                                                   Piou + (size_t)ps * B_ * PIOU_N, PIOU_N);
        }
        // Pf[children] = h @ Wfh        (M = nc*512, N = 384)
        {
            dim3 grid(PF_N / 128, nc * 4);
            gemm_m<<<grid, GT_THREADS, SMEM_DYN>>>(hh, hl, cs, wfh2h, wfh2l, nullptr,
                                                   Pf + (size_t)cs * B_ * PF_N, PF_N);
        }
        comb_k<<<(np * B_ * D_ + 255) / 256, 256>>>(ps, np, out);
    }
    (void)in_sizes; (void)n_in; (void)out_size;
}

// round 10
// speedup vs baseline: 1.1799x; 1.1799x over previous
#include <cuda_runtime.h>
#include <cuda_bf16.h>
#include <cstdint>

#define B_  512
#define N_  127
#define D_  300
#define FD  1200    // 4*D : [i | o | u | f]
#define FDP 1280    // padded col stride for Z (10 tiles of 128)
#define PIOU_N 1024 // padded col count for Piou (900 used: [i|o|u] at 0/300/600)
#define PF_N   384  // padded col count for Pf (300 used)
#define AK  320     // padded K stride (10 chunks of 32)
#define WK  320

// ---------------- scratch (static device allocations) ----------------
__device__ float g_Z[(size_t)N_ * B_ * FDP];          // x @ [Wioux|Wfx] + bias
__device__ float g_Piou[(size_t)63 * B_ * PIOU_N];    // hsum @ Wiouh   (parents 0..62)
__device__ float g_Pf[(size_t)N_ * B_ * PF_N];        // h @ Wfh        (children 1..126)
__device__ float g_C[(size_t)N_ * B_ * D_];           // cell states
__device__ unsigned short g_x_hi[(size_t)N_ * B_ * AK];
__device__ unsigned short g_x_lo[(size_t)N_ * B_ * AK];
__device__ unsigned short g_h_hi[(size_t)N_ * B_ * AK];
__device__ unsigned short g_h_lo[(size_t)N_ * B_ * AK];
__device__ unsigned short g_hs_hi[(size_t)N_ * B_ * AK];   // children h-sum (parents)
__device__ unsigned short g_hs_lo[(size_t)N_ * B_ * AK];
__device__ unsigned short g_WtC_hi[FDP * WK];         // [Wioux|Wfx]^T  (n-major, k-contig)
__device__ unsigned short g_WtC_lo[FDP * WK];
__device__ unsigned short g_Wiou2_hi[PIOU_N * WK];    // Wiouh^T
__device__ unsigned short g_Wiou2_lo[PIOU_N * WK];
__device__ unsigned short g_Wfh2_hi[PF_N * WK];       // Wfh^T
__device__ unsigned short g_Wfh2_lo[PF_N * WK];
__device__ float g_bc[FDP];                           // combined bias for Z (pads zero)

__device__ __forceinline__ float sigm(float x) { return 1.0f / (1.0f + __expf(-x)); }

// ---------------- PTX helpers (sm_80-era; compile on plain sm_103) ----------------
__device__ __forceinline__ uint32_t smem_u32(const void* p) {
    uint32_t a;
    asm("{ .reg .u64 t; cvta.to.shared.u64 t, %1; cvt.u32.u64 %0, t; }" : "=r"(a) : "l"(p));
    return a;
}
__device__ __forceinline__ void cp16(uint32_t dst, const void* src) {
    uint64_t gsrc;
    asm("cvta.to.global.u64 %0, %1;" : "=l"(gsrc) : "l"(src));
    asm volatile("cp.async.cg.shared.global [%0], [%1], 16;" :: "r"(dst), "l"(gsrc));
}
#define CP_COMMIT() asm volatile("cp.async.commit_group;" ::: "memory")
#define CP_WAIT(n)  asm volatile("cp.async.wait_group %0;" :: "n"(n) : "memory")

__device__ __forceinline__ void ldsm4(uint32_t* r, uint32_t addr) {
    asm volatile("ldmatrix.sync.aligned.m8n8.x4.shared.b16 {%0,%1,%2,%3}, [%4];"
                 : "=r"(r[0]), "=r"(r[1]), "=r"(r[2]), "=r"(r[3]) : "r"(addr));
}
__device__ __forceinline__ void mma16816(float* c, const uint32_t* a, uint32_t b0, uint32_t b1) {
    asm volatile(
        "mma.sync.aligned.m16n8k16.row.col.f32.bf16.bf16.f32 "
        "{%0,%1,%2,%3}, {%4,%5,%6,%7}, {%8,%9}, {%0,%1,%2,%3};"
        : "+f"(c[0]), "+f"(c[1]), "+f"(c[2]), "+f"(c[3])
        : "r"(a[0]), "r"(a[1]), "r"(a[2]), "r"(a[3]), "r"(b0), "r"(b1));
}

// ---------------- pack weights: transpose + bf16 hi/lo split + combined bias ----------------
__global__ void pack_k(const float* __restrict__ Wioux, const float* __restrict__ bioux,
                       const float* __restrict__ Wiouh, const float* __restrict__ biouh,
                       const float* __restrict__ Wfx,  const float* __restrict__ bfx,
                       const float* __restrict__ Wfh,  const float* __restrict__ bfh) {
    int idx = blockIdx.x * blockDim.x + threadIdx.x;
    if (idx >= FDP * WK) return;
    int n = idx / WK, k = idx % WK;

    {
        float wc = 0.0f;
        if (k < D_ && n < FD) {
            wc = (n < 3 * D_) ? Wioux[k * 3 * D_ + n] : Wfx[k * D_ + n - 3 * D_];
        }
        __nv_bfloat16 h = __float2bfloat16(wc);
        g_WtC_hi[idx] = __bfloat16_as_ushort(h);
        g_WtC_lo[idx] = __bfloat16_as_ushort(__float2bfloat16(wc - __bfloat162float(h)));
    }
    if (n < PIOU_N) {
        float w = (k < D_ && n < 3 * D_) ? Wiouh[k * 3 * D_ + n] : 0.0f;
        __nv_bfloat16 h = __float2bfloat16(w);
        g_Wiou2_hi[n * WK + k] = __bfloat16_as_ushort(h);
        g_Wiou2_lo[n * WK + k] = __bfloat16_as_ushort(__float2bfloat16(w - __bfloat162float(h)));
    }
    if (n < PF_N) {
        float w = (k < D_ && n < D_) ? Wfh[k * D_ + n] : 0.0f;
        __nv_bfloat16 h = __float2bfloat16(w);
        g_Wfh2_hi[n * WK + k] = __bfloat16_as_ushort(h);
        g_Wfh2_lo[n * WK + k] = __bfloat16_as_ushort(__float2bfloat16(w - __bfloat162float(h)));
    }
    if (idx < FDP)
        g_bc[idx] = (idx >= FD) ? 0.0f
                  : (idx < 3 * D_) ? (bioux[idx] + biouh[idx])
                                   : (bfx[idx - 3 * D_] + bfh[idx - 3 * D_]);
}

// ---------------- convert x (fp32) -> bf16 hi/lo, padded K stride ----------------
__global__ void xconv_k(const float* __restrict__ x) {
    int idx = blockIdx.x * blockDim.x + threadIdx.x;
    const int pairs = AK / 2;                       // 160
    if (idx >= N_ * B_ * pairs) return;
    int r  = idx / pairs;
    int k  = (idx % pairs) * 2;
    if (k >= D_) return;                            // pads stay zero (static init)
    float a0 = x[(size_t)r * D_ + k];
    float a1 = x[(size_t)r * D_ + k + 1];
    __nv_bfloat16 h0 = __float2bfloat16(a0);
    __nv_bfloat16 h1 = __float2bfloat16(a1);
    __nv_bfloat16 l0 = __float2bfloat16(a0 - __bfloat162float(h0));
    __nv_bfloat16 l1 = __float2bfloat16(a1 - __bfloat162float(h1));
    uint32_t hh = (uint32_t)__bfloat16_as_ushort(h0) | ((uint32_t)__bfloat16_as_ushort(h1) << 16);
    uint32_t ll = (uint32_t)__bfloat16_as_ushort(l0) | ((uint32_t)__bfloat16_as_ushort(l1) << 16);
    *(uint32_t*)(g_x_hi + (size_t)r * AK + k) = hh;
    *(uint32_t*)(g_x_lo + (size_t)r * AK + k) = ll;
}

// ---------------- child h-sum for parents, split to bf16 hi/lo ----------------
__global__ void hsum_k(int pstart, int n, const float* __restrict__ hsrc) {
    int idx = blockIdx.x * blockDim.x + threadIdx.x;
    int total = n * B_ * D_;
    if (idx >= total) return;
    int d  = idx % D_;
    int rb = idx / D_;
    int b  = rb % B_;
    int j  = pstart + rb / B_;
    int a  = 2 * j + 1, a2 = 2 * j + 2;
    float s = hsrc[((size_t)b * N_ + a) * D_ + d] + hsrc[((size_t)b * N_ + a2) * D_ + d];
    __nv_bfloat16 hb = __float2bfloat16(s);
    size_t ro = (size_t)b * N_ + j;
    g_hs_hi[ro * AK + d] = __bfloat16_as_ushort(hb);
    g_hs_lo[ro * AK + d] = __bfloat16_as_ushort(__float2bfloat16(s - __bfloat162float(hb)));
}

// ---------------- mma.sync split-bf16 GEMM tile body ----------------
// Block tile 128x128, K-tile 32, 2-stage cp.async pipeline (2 CTAs/SM),
// 8 warps (2m x 4n), warp tile 64x32, m16n8k16 bf16, 3-term split fp32 accum.
#define GT_THREADS 256
#define SROW 40                     // padded smem row (bf16 elems) = 80B, conflict-free
#define TILE_B (128 * SROW * 2)     // 10240 bytes per (buf) tile
#define STAGE_B (4 * TILE_B)        // Ahi,Alo,Bhi,Blo
#define SMEM_DYN (2 * STAGE_B)      // 81920 -> 2 CTAs/SM

__device__ __forceinline__ void gemm_tile_body(
    uint32_t sbase, int t, int row0, int col0,
    const unsigned short* __restrict__ Ahi, const unsigned short* __restrict__ Alo,
    int node_start,
    const unsigned short* __restrict__ Bhi, const unsigned short* __restrict__ Blo,
    const float* __restrict__ bias, float* __restrict__ Out, int ostride)
{
    const int wid = t >> 5, lid = t & 31;
    const int wm = (wid >> 2) * 64;      // warp m offset (0/64)
    const int wn = (wid & 3) * 32;       // warp n offset (0/32/64/96)

    float acc[4][4][4];
#pragma unroll
    for (int i = 0; i < 4; i++)
#pragma unroll
        for (int j = 0; j < 4; j++)
#pragma unroll
            for (int k = 0; k < 4; k++) acc[i][j][k] = 0.0f;

    auto load_stage = [&](int slot, int kt) {
        uint32_t sb = sbase + slot * STAGE_B;
#pragma unroll
        for (int i = 0; i < 4; ++i) {
            int idx = i * GT_THREADS + t;          // 0..1023
            int buf = idx >> 9;                    // 0=hi 1=lo
            int rem = idx & 511;
            int row = rem >> 2, part = rem & 3;
            int R = row0 + row;
            int j = node_start + (R >> 9);
            int b = R & (B_ - 1);
            const unsigned short* src =
                (buf ? Alo : Ahi) + ((size_t)b * N_ + j) * AK + kt + part * 8;
            cp16(sb + buf * TILE_B + row * (SROW * 2) + part * 16, src);
        }
#pragma unroll
        for (int i = 0; i < 4; ++i) {
            int idx = i * GT_THREADS + t;
            int buf = idx >> 9;
            int rem = idx & 511;
            int row = rem >> 2, part = rem & 3;
            const unsigned short* src =
                (buf ? Blo : Bhi) + (size_t)(col0 + row) * WK + kt + part * 8;
            cp16(sb + 2 * TILE_B + buf * TILE_B + row * (SROW * 2) + part * 16, src);
        }
    };

    const int lr = lid & 15, lc = (lid >> 4) * 8;
    auto compute_stage = [&](int slot) {
        uint32_t sA = sbase + slot * STAGE_B;
        uint32_t sB = sA + 2 * TILE_B;
#pragma unroll
        for (int ks = 0; ks < 32; ks += 16) {
            uint32_t a_hi[4][4], a_lo[4][4];
#pragma unroll
            for (int mt = 0; mt < 4; ++mt) {
                uint32_t ad = sA + ((wm + mt * 16 + lr) * SROW + ks + lc) * 2;
                ldsm4(a_hi[mt], ad);
                ldsm4(a_lo[mt], ad + TILE_B);
            }
            uint32_t b_hi[2][4], b_lo[2][4];
#pragma unroll
            for (int nh = 0; nh < 2; ++nh) {
                uint32_t bd = sB + ((wn + nh * 16 + lr) * SROW + ks + lc) * 2;
                ldsm4(b_hi[nh], bd);
                ldsm4(b_lo[nh], bd + TILE_B);
            }
#pragma unroll
            for (int mt = 0; mt < 4; ++mt)
#pragma unroll
                for (int nt = 0; nt < 4; ++nt) {
                    uint32_t bh0 = b_hi[nt >> 1][nt & 1], bh1 = b_hi[nt >> 1][(nt & 1) + 2];
                    uint32_t bl0 = b_lo[nt >> 1][nt & 1], bl1 = b_lo[nt >> 1][(nt & 1) + 2];
                    mma16816(acc[mt][nt], a_hi[mt], bh0, bh1);
                    mma16816(acc[mt][nt], a_hi[mt], bl0, bl1);
                    mma16816(acc[mt][nt], a_lo[mt], bh0, bh1);
                }
        }
    };

    // ---- pipeline: 10 K-iterations, 2 stages (R4-proven) ----
    load_stage(0, 0);
    CP_COMMIT();
#pragma unroll 1
    for (int it = 0; it < 10; ++it) {
        if (it + 1 < 10) {
            load_stage((it + 1) & 1, (it + 1) * 32);
            CP_COMMIT();
            CP_WAIT(1);
        } else {
            CP_WAIT(0);
        }
        __syncthreads();
        compute_stage(it & 1);
        __syncthreads();
    }

    // ---- epilogue ----
    const int g = lid >> 2, i4 = lid & 3;
#pragma unroll
    for (int mt = 0; mt < 4; ++mt) {
        int r0 = row0 + wm + mt * 16 + g;
#pragma unroll
        for (int nt = 0; nt < 4; ++nt) {
            int cc = col0 + wn + nt * 8 + i4 * 2;
            float b0v = 0.0f, b1v = 0.0f;
            if (bias) { b0v = bias[cc]; b1v = bias[cc + 1]; }
            float* o0 = Out + (size_t)r0 * ostride + cc;
            float* o1 = Out + (size_t)(r0 + 8) * ostride + cc;
            o0[0] = acc[mt][nt][0] + b0v;
            o0[1] = acc[mt][nt][1] + b1v;
            o1[0] = acc[mt][nt][2] + b0v;
            o1[1] = acc[mt][nt][3] + b1v;
        }
    }
}

// Z GEMM: blockIdx.x = col tile (L2 A-reuse), blockIdx.y = row tile
__global__ __launch_bounds__(GT_THREADS) void gemm_m(
    const unsigned short* __restrict__ Ahi, const unsigned short* __restrict__ Alo,
    int node_start,
    const unsigned short* __restrict__ Bhi, const unsigned short* __restrict__ Blo,
    const float* __restrict__ bias, float* __restrict__ Out, int ostride)
{
    extern __shared__ char dsm[];
    gemm_tile_body(smem_u32(dsm), threadIdx.x,
                   blockIdx.y * 128, blockIdx.x * 128,
                   Ahi, Alo, node_start, Bhi, Blo, bias, Out, ostride);
}

// Merged two-job GEMM (one launch per tree level): flat grid, job0 = Piou, job1 = Pf.
__global__ __launch_bounds__(GT_THREADS) void gemm2_k(
    const unsigned short* __restrict__ A0h, const unsigned short* __restrict__ A0l,
    int ns0, const unsigned short* __restrict__ B0h, const unsigned short* __restrict__ B0l,
    float* __restrict__ O0, int ostride0, int nct0, int tiles0,
    const unsigned short* __restrict__ A1h, const unsigned short* __restrict__ A1l,
    int ns1, const unsigned short* __restrict__ B1h, const unsigned short* __restrict__ B1l,
    float* __restrict__ O1, int ostride1, int nct1)
{
    extern __shared__ char dsm[];
    int id = blockIdx.x;
    if (id < tiles0) {
        int row0 = (id / nct0) * 128, col0 = (id % nct0) * 128;
        gemm_tile_body(smem_u32(dsm), threadIdx.x, row0, col0,
                       A0h, A0l, ns0, B0h, B0l, nullptr, O0, ostride0);
    } else {
        id -= tiles0;
        int row0 = (id / nct1) * 128, col0 = (id % nct1) * 128;
        gemm_tile_body(smem_u32(dsm), threadIdx.x, row0, col0,
                       A1h, A1l, ns1, B1h, B1l, nullptr, O1, ostride1);
    }
}

// ---------------- leaves: c = sig(z_i)*tanh(z_u); h = sig(z_o)*tanh(c) ----------------
__global__ void leaf_k(float* __restrict__ out) {
    int idx = blockIdx.x * blockDim.x + threadIdx.x;
    const int total = 64 * B_ * D_;
    if (idx >= total) return;
    int d  = idx % D_;
    int rb = idx / D_;
    int b  = rb % B_;
    int j  = 63 + rb / B_;
    size_t zr = ((size_t)j * B_ + b) * FDP;
    float i_ = sigm(g_Z[zr + d]);
    float o_ = sigm(g_Z[zr + D_ + d]);
    float u_ = tanhf(g_Z[zr + 2 * D_ + d]);
    float c  = i_ * u_;
    g_C[((size_t)j * B_ + b) * D_ + d] = c;
    float hh = o_ * tanhf(c);
    size_t ro = (size_t)b * N_ + j;
    out[ro * D_ + d] = hh;
    __nv_bfloat16 hb = __float2bfloat16(hh);
    g_h_hi[ro * AK + d] = __bfloat16_as_ushort(hb);
    g_h_lo[ro * AK + d] = __bfloat16_as_ushort(__float2bfloat16(hh - __bfloat162float(hb)));
}

// ---------------- internal level combine ----------------
__global__ void comb_k(int start, int n, float* __restrict__ out) {
    int idx = blockIdx.x * blockDim.x + threadIdx.x;
    int total = n * B_ * D_;
    if (idx >= total) return;
    int d  = idx % D_;
    int rb = idx / D_;
    int b  = rb % B_;
    int j  = start + rb / B_;
    int a  = 2 * j + 1;
    int a2 = 2 * j + 2;
    size_t zr = ((size_t)j  * B_ + b) * FDP;
    size_t pj = ((size_t)j  * B_ + b) * PIOU_N;
    size_t pa = ((size_t)a  * B_ + b) * PF_N;
    size_t pb = ((size_t)a2 * B_ + b) * PF_N;

    float ii = sigm (g_Z[zr + d]          + g_Piou[pj + d]);
    float oo = sigm (g_Z[zr + D_ + d]     + g_Piou[pj + D_ + d]);
    float uu = tanhf(g_Z[zr + 2*D_ + d]   + g_Piou[pj + 2*D_ + d]);
    float zf = g_Z[zr + 3 * D_ + d];
    float fa = sigm(g_Pf[pa + d] + zf);
    float fb = sigm(g_Pf[pb + d] + zf);

    float ca = g_C[((size_t)a  * B_ + b) * D_ + d];
    float cb = g_C[((size_t)a2 * B_ + b) * D_ + d];
    float cc = ii * uu + fa * ca + fb * cb;
    g_C[((size_t)j * B_ + b) * D_ + d] = cc;
    float hh = oo * tanhf(cc);
    size_t ro = (size_t)b * N_ + j;
    out[ro * D_ + d] = hh;
    __nv_bfloat16 hb = __float2bfloat16(hh);
    g_h_hi[ro * AK + d] = __bfloat16_as_ushort(hb);
    g_h_lo[ro * AK + d] = __bfloat16_as_ushort(__float2bfloat16(hh - __bfloat162float(hb)));
}

extern "C" void kernel_launch(void* const* d_in, const int* in_sizes, int n_in,
                              void* d_out, int out_size) {
    const float* x     = (const float*)d_in[0];
    const float* Wioux = (const float*)d_in[1];
    const float* bioux = (const float*)d_in[2];
    const float* Wiouh = (const float*)d_in[3];
    const float* biouh = (const float*)d_in[4];
    const float* Wfx   = (const float*)d_in[5];
    const float* bfx   = (const float*)d_in[6];
    const float* Wfh   = (const float*)d_in[7];
    const float* bfh   = (const float*)d_in[8];
    float* out = (float*)d_out;

    float *Zp, *Piou, *Pf, *bcp;
    unsigned short *xh, *xl, *hh, *hl, *hsh, *hsl, *wch, *wcl, *wi2h, *wi2l, *wfh2h, *wfh2l;
    cudaGetSymbolAddress((void**)&Zp,    g_Z);
    cudaGetSymbolAddress((void**)&Piou,  g_Piou);
    cudaGetSymbolAddress((void**)&Pf,    g_Pf);
    cudaGetSymbolAddress((void**)&bcp,   g_bc);
    cudaGetSymbolAddress((void**)&xh,    g_x_hi);
    cudaGetSymbolAddress((void**)&xl,    g_x_lo);
    cudaGetSymbolAddress((void**)&hh,    g_h_hi);
    cudaGetSymbolAddress((void**)&hl,    g_h_lo);
    cudaGetSymbolAddress((void**)&hsh,   g_hs_hi);
    cudaGetSymbolAddress((void**)&hsl,   g_hs_lo);
    cudaGetSymbolAddress((void**)&wch,   g_WtC_hi);
    cudaGetSymbolAddress((void**)&wcl,   g_WtC_lo);
    cudaGetSymbolAddress((void**)&wi2h,  g_Wiou2_hi);
    cudaGetSymbolAddress((void**)&wi2l,  g_Wiou2_lo);
    cudaGetSymbolAddress((void**)&wfh2h, g_Wfh2_hi);
    cudaGetSymbolAddress((void**)&wfh2l, g_Wfh2_lo);

    cudaFuncSetAttribute(gemm_m,  cudaFuncAttributeMaxDynamicSharedMemorySize, SMEM_DYN);
    cudaFuncSetAttribute(gemm2_k, cudaFuncAttributeMaxDynamicSharedMemorySize, SMEM_DYN);

    // 1. pack weights (transpose + split) + combined bias
    pack_k<<<(FDP * WK + 255) / 256, 256>>>(Wioux, bioux, Wiouh, biouh, Wfx, bfx, Wfh, bfh);

    // 2. split x into bf16 hi/lo
    xconv_k<<<(N_ * B_ * (AK / 2) + 255) / 256, 256>>>(x);

    // 3. Z = x @ [Wioux|Wfx] + bias, all nodes  (M = 65024, N = 1280)
    {
        dim3 grid(FDP / 128, (N_ * B_) / 128);
        gemm_m<<<grid, GT_THREADS, SMEM_DYN>>>(xh, xl, 0, wch, wcl, bcp, Zp, FDP);
    }

    // 4. leaves (nodes 63..126)
    leaf_k<<<(64 * B_ * D_ + 255) / 256, 256>>>(out);

    // 5. levels: parents pl = 5 .. 0 (children at pl+1 already have h)
    for (int pl = 5; pl >= 0; --pl) {
        int ps = (1 << pl) - 1, np = 1 << pl;             // parent start/count
        int cs = (1 << (pl + 1)) - 1, nc = 1 << (pl + 1); // child start/count

        hsum_k<<<(np * B_ * D_ + 255) / 256, 256>>>(ps, np, out);

        // one merged launch: Piou[parents] = hsum @ Wiouh  (rows np*512, cols 1024)
        //                  + Pf[children]  = h @ Wfh       (rows nc*512, cols 384)
        int tiles0 = (np * 4) * (PIOU_N / 128);   // 32*np
        int tiles1 = (nc * 4) * (PF_N / 128);     // 24*np
        gemm2_k<<<tiles0 + tiles1, GT_THREADS, SMEM_DYN>>>(
            hsh, hsl, ps, wi2h, wi2l, Piou + (size_t)ps * B_ * PIOU_N, PIOU_N, PIOU_N / 128, tiles0,
            hh,  hl,  cs, wfh2h, wfh2l, Pf  + (size_t)cs * B_ * PF_N,  PF_N,  PF_N / 128);

        comb_k<<<(np * B_ * D_ + 255) / 256, 256>>>(ps, np, out);
    }
    (void)in_sizes; (void)n_in; (void)out_size;
}

// round 12
// speedup vs baseline: 1.3262x; 1.1241x over previous
#include <cuda_runtime.h>
#include <cuda_bf16.h>
#include <cstdint>

#define B_  512
#define N_  127
#define D_  300
#define FD  1200    // 4*D : [i | o | u | f]
#define FDP 1280    // padded col stride for Z (10 tiles of 128)
#define PIOU_N 1024 // padded col count for Piou (900 used: [i|o|u] at 0/300/600)
#define PF_N   384  // padded col count for Pf (300 used)
#define AK  320     // padded K stride (10 chunks of 32)
#define WK  320

// ---------------- scratch (static device allocations) ----------------
__device__ float g_Z[(size_t)N_ * B_ * FDP];          // x @ [Wioux|Wfx] + bias
__device__ float g_Piou[(size_t)63 * B_ * PIOU_N];    // hsum @ Wiouh   (parents 0..62)
__device__ float g_Pf[(size_t)N_ * B_ * PF_N];        // h @ Wfh        (children 1..126)
__device__ float g_C[(size_t)N_ * B_ * D_];           // cell states
__device__ unsigned short g_x_hi[(size_t)N_ * B_ * AK];
__device__ unsigned short g_x_lo[(size_t)N_ * B_ * AK];
__device__ unsigned short g_h_hi[(size_t)N_ * B_ * AK];
__device__ unsigned short g_h_lo[(size_t)N_ * B_ * AK];
__device__ unsigned short g_hs_hi[(size_t)N_ * B_ * AK];   // children h-sum (parents)
__device__ unsigned short g_hs_lo[(size_t)N_ * B_ * AK];
__device__ unsigned short g_WtC_hi[FDP * WK];         // [Wioux|Wfx]^T  (n-major, k-contig)
__device__ unsigned short g_WtC_lo[FDP * WK];
__device__ unsigned short g_Wiou2_hi[PIOU_N * WK];    // Wiouh^T
__device__ unsigned short g_Wiou2_lo[PIOU_N * WK];
__device__ unsigned short g_Wfh2_hi[PF_N * WK];       // Wfh^T
__device__ unsigned short g_Wfh2_lo[PF_N * WK];
__device__ float g_bc[FDP];                           // combined bias for Z (pads zero)

__device__ __forceinline__ float sigm(float x) { return 1.0f / (1.0f + __expf(-x)); }

__device__ __forceinline__ uint32_t pack_bf16_hi2(float x, float y) {
    __nv_bfloat16 hx = __float2bfloat16(x);
    __nv_bfloat16 hy = __float2bfloat16(y);
    return (uint32_t)__bfloat16_as_ushort(hx) | ((uint32_t)__bfloat16_as_ushort(hy) << 16);
}
__device__ __forceinline__ uint32_t pack_bf16_lo2(float x, float y) {
    __nv_bfloat16 hx = __float2bfloat16(x);
    __nv_bfloat16 hy = __float2bfloat16(y);
    __nv_bfloat16 lx = __float2bfloat16(x - __bfloat162float(hx));
    __nv_bfloat16 ly = __float2bfloat16(y - __bfloat162float(hy));
    return (uint32_t)__bfloat16_as_ushort(lx) | ((uint32_t)__bfloat16_as_ushort(ly) << 16);
}

// ---------------- PTX helpers (sm_80-era; compile on plain sm_103) ----------------
__device__ __forceinline__ uint32_t smem_u32(const void* p) {
    uint32_t a;
    asm("{ .reg .u64 t; cvta.to.shared.u64 t, %1; cvt.u32.u64 %0, t; }" : "=r"(a) : "l"(p));
    return a;
}
__device__ __forceinline__ void cp16(uint32_t dst, const void* src) {
    uint64_t gsrc;
    asm("cvta.to.global.u64 %0, %1;" : "=l"(gsrc) : "l"(src));
    asm volatile("cp.async.cg.shared.global [%0], [%1], 16;" :: "r"(dst), "l"(gsrc));
}
#define CP_COMMIT() asm volatile("cp.async.commit_group;" ::: "memory")
#define CP_WAIT(n)  asm volatile("cp.async.wait_group %0;" :: "n"(n) : "memory")

__device__ __forceinline__ void ldsm4(uint32_t* r, uint32_t addr) {
    asm volatile("ldmatrix.sync.aligned.m8n8.x4.shared.b16 {%0,%1,%2,%3}, [%4];"
                 : "=r"(r[0]), "=r"(r[1]), "=r"(r[2]), "=r"(r[3]) : "r"(addr));
}
__device__ __forceinline__ void mma16816(float* c, const uint32_t* a, uint32_t b0, uint32_t b1) {
    asm volatile(
        "mma.sync.aligned.m16n8k16.row.col.f32.bf16.bf16.f32 "
        "{%0,%1,%2,%3}, {%4,%5,%6,%7}, {%8,%9}, {%0,%1,%2,%3};"
        : "+f"(c[0]), "+f"(c[1]), "+f"(c[2]), "+f"(c[3])
        : "r"(a[0]), "r"(a[1]), "r"(a[2]), "r"(a[3]), "r"(b0), "r"(b1));
}

// ---------------- pack weights: transpose + bf16 hi/lo split + combined bias ----------------
__global__ void pack_k(const float* __restrict__ Wioux, const float* __restrict__ bioux,
                       const float* __restrict__ Wiouh, const float* __restrict__ biouh,
                       const float* __restrict__ Wfx,  const float* __restrict__ bfx,
                       const float* __restrict__ Wfh,  const float* __restrict__ bfh) {
    int idx = blockIdx.x * blockDim.x + threadIdx.x;
    if (idx >= FDP * WK) return;
    int n = idx / WK, k = idx % WK;

    {
        float wc = 0.0f;
        if (k < D_ && n < FD) {
            wc = (n < 3 * D_) ? Wioux[k * 3 * D_ + n] : Wfx[k * D_ + n - 3 * D_];
        }
        __nv_bfloat16 h = __float2bfloat16(wc);
        g_WtC_hi[idx] = __bfloat16_as_ushort(h);
        g_WtC_lo[idx] = __bfloat16_as_ushort(__float2bfloat16(wc - __bfloat162float(h)));
    }
    if (n < PIOU_N) {
        float w = (k < D_ && n < 3 * D_) ? Wiouh[k * 3 * D_ + n] : 0.0f;
        __nv_bfloat16 h = __float2bfloat16(w);
        g_Wiou2_hi[n * WK + k] = __bfloat16_as_ushort(h);
        g_Wiou2_lo[n * WK + k] = __bfloat16_as_ushort(__float2bfloat16(w - __bfloat162float(h)));
    }
    if (n < PF_N) {
        float w = (k < D_ && n < D_) ? Wfh[k * D_ + n] : 0.0f;
        __nv_bfloat16 h = __float2bfloat16(w);
        g_Wfh2_hi[n * WK + k] = __bfloat16_as_ushort(h);
        g_Wfh2_lo[n * WK + k] = __bfloat16_as_ushort(__float2bfloat16(w - __bfloat162float(h)));
    }
    if (idx < FDP)
        g_bc[idx] = (idx >= FD) ? 0.0f
                  : (idx < 3 * D_) ? (bioux[idx] + biouh[idx])
                                   : (bfx[idx - 3 * D_] + bfh[idx - 3 * D_]);
}

// ---------------- convert x (fp32) -> bf16 hi/lo, padded K stride ----------------
__global__ void xconv_k(const float* __restrict__ x) {
    int idx = blockIdx.x * blockDim.x + threadIdx.x;
    const int pairs = AK / 2;                       // 160
    if (idx >= N_ * B_ * pairs) return;
    int r  = idx / pairs;
    int k  = (idx % pairs) * 2;
    if (k >= D_) return;                            // pads stay zero (static init)
    float a0 = x[(size_t)r * D_ + k];
    float a1 = x[(size_t)r * D_ + k + 1];
    *(uint32_t*)(g_x_hi + (size_t)r * AK + k) = pack_bf16_hi2(a0, a1);
    *(uint32_t*)(g_x_lo + (size_t)r * AK + k) = pack_bf16_lo2(a0, a1);
}

// ---------------- mma.sync split-bf16 GEMM tile body (identical to R10) ----------------
#define GT_THREADS 256
#define SROW 40                     // padded smem row (bf16 elems) = 80B, conflict-free
#define TILE_B (128 * SROW * 2)     // 10240 bytes per (buf) tile
#define STAGE_B (4 * TILE_B)        // Ahi,Alo,Bhi,Blo
#define SMEM_DYN (2 * STAGE_B)      // 81920 -> 2 CTAs/SM

__device__ __forceinline__ void gemm_tile_body(
    uint32_t sbase, int t, int row0, int col0,
    const unsigned short* __restrict__ Ahi, const unsigned short* __restrict__ Alo,
    int node_start,
    const unsigned short* __restrict__ Bhi, const unsigned short* __restrict__ Blo,
    const float* __restrict__ bias, float* __restrict__ Out, int ostride)
{
    const int wid = t >> 5, lid = t & 31;
    const int wm = (wid >> 2) * 64;      // warp m offset (0/64)
    const int wn = (wid & 3) * 32;       // warp n offset (0/32/64/96)

    float acc[4][4][4];
#pragma unroll
    for (int i = 0; i < 4; i++)
#pragma unroll
        for (int j = 0; j < 4; j++)
#pragma unroll
            for (int k = 0; k < 4; k++) acc[i][j][k] = 0.0f;

    auto load_stage = [&](int slot, int kt) {
        uint32_t sb = sbase + slot * STAGE_B;
#pragma unroll
        for (int i = 0; i < 4; ++i) {
            int idx = i * GT_THREADS + t;          // 0..1023
            int buf = idx >> 9;                    // 0=hi 1=lo
            int rem = idx & 511;
            int row = rem >> 2, part = rem & 3;
            int R = row0 + row;
            int j = node_start + (R >> 9);
            int b = R & (B_ - 1);
            const unsigned short* src =
                (buf ? Alo : Ahi) + ((size_t)b * N_ + j) * AK + kt + part * 8;
            cp16(sb + buf * TILE_B + row * (SROW * 2) + part * 16, src);
        }
#pragma unroll
        for (int i = 0; i < 4; ++i) {
            int idx = i * GT_THREADS + t;
            int buf = idx >> 9;
            int rem = idx & 511;
            int row = rem >> 2, part = rem & 3;
            const unsigned short* src =
                (buf ? Blo : Bhi) + (size_t)(col0 + row) * WK + kt + part * 8;
            cp16(sb + 2 * TILE_B + buf * TILE_B + row * (SROW * 2) + part * 16, src);
        }
    };

    const int lr = lid & 15, lc = (lid >> 4) * 8;
    auto compute_stage = [&](int slot) {
        uint32_t sA = sbase + slot * STAGE_B;
        uint32_t sB = sA + 2 * TILE_B;
#pragma unroll
        for (int ks = 0; ks < 32; ks += 16) {
            uint32_t a_hi[4][4], a_lo[4][4];
#pragma unroll
            for (int mt = 0; mt < 4; ++mt) {
                uint32_t ad = sA + ((wm + mt * 16 + lr) * SROW + ks + lc) * 2;
                ldsm4(a_hi[mt], ad);
                ldsm4(a_lo[mt], ad + TILE_B);
            }
            uint32_t b_hi[2][4], b_lo[2][4];
#pragma unroll
            for (int nh = 0; nh < 2; ++nh) {
                uint32_t bd = sB + ((wn + nh * 16 + lr) * SROW + ks + lc) * 2;
                ldsm4(b_hi[nh], bd);
                ldsm4(b_lo[nh], bd + TILE_B);
            }
#pragma unroll
            for (int mt = 0; mt < 4; ++mt)
#pragma unroll
                for (int nt = 0; nt < 4; ++nt) {
                    uint32_t bh0 = b_hi[nt >> 1][nt & 1], bh1 = b_hi[nt >> 1][(nt & 1) + 2];
                    uint32_t bl0 = b_lo[nt >> 1][nt & 1], bl1 = b_lo[nt >> 1][(nt & 1) + 2];
                    mma16816(acc[mt][nt], a_hi[mt], bh0, bh1);
                    mma16816(acc[mt][nt], a_hi[mt], bl0, bl1);
                    mma16816(acc[mt][nt], a_lo[mt], bh0, bh1);
                }
        }
    };

    load_stage(0, 0);
    CP_COMMIT();
#pragma unroll 1
    for (int it = 0; it < 10; ++it) {
        if (it + 1 < 10) {
            load_stage((it + 1) & 1, (it + 1) * 32);
            CP_COMMIT();
            CP_WAIT(1);
        } else {
            CP_WAIT(0);
        }
        __syncthreads();
        compute_stage(it & 1);
        __syncthreads();
    }

    const int g = lid >> 2, i4 = lid & 3;
#pragma unroll
    for (int mt = 0; mt < 4; ++mt) {
        int r0 = row0 + wm + mt * 16 + g;
#pragma unroll
        for (int nt = 0; nt < 4; ++nt) {
            int cc = col0 + wn + nt * 8 + i4 * 2;
            float b0v = 0.0f, b1v = 0.0f;
            if (bias) { b0v = bias[cc]; b1v = bias[cc + 1]; }
            float* o0 = Out + (size_t)r0 * ostride + cc;
            float* o1 = Out + (size_t)(r0 + 8) * ostride + cc;
            o0[0] = acc[mt][nt][0] + b0v;
            o0[1] = acc[mt][nt][1] + b1v;
            o1[0] = acc[mt][nt][2] + b0v;
            o1[1] = acc[mt][nt][3] + b1v;
        }
    }
}

// Z GEMM: blockIdx.x = col tile (L2 A-reuse), blockIdx.y = row tile
__global__ __launch_bounds__(GT_THREADS) void gemm_m(
    const unsigned short* __restrict__ Ahi, const unsigned short* __restrict__ Alo,
    int node_start,
    const unsigned short* __restrict__ Bhi, const unsigned short* __restrict__ Blo,
    const float* __restrict__ bias, float* __restrict__ Out, int ostride)
{
    extern __shared__ char dsm[];
    gemm_tile_body(smem_u32(dsm), threadIdx.x,
                   blockIdx.y * 128, blockIdx.x * 128,
                   Ahi, Alo, node_start, Bhi, Blo, bias, Out, ostride);
}

// Merged two-job GEMM (one launch per tree level): flat grid, job0 = Piou, job1 = Pf.
__global__ __launch_bounds__(GT_THREADS) void gemm2_k(
    const unsigned short* __restrict__ A0h, const unsigned short* __restrict__ A0l,
    int ns0, const unsigned short* __restrict__ B0h, const unsigned short* __restrict__ B0l,
    float* __restrict__ O0, int ostride0, int nct0, int tiles0,
    const unsigned short* __restrict__ A1h, const unsigned short* __restrict__ A1l,
    int ns1, const unsigned short* __restrict__ B1h, const unsigned short* __restrict__ B1l,
    float* __restrict__ O1, int ostride1, int nct1)
{
    extern __shared__ char dsm[];
    int id = blockIdx.x;
    if (id < tiles0) {
        int row0 = (id / nct0) * 128, col0 = (id % nct0) * 128;
        gemm_tile_body(smem_u32(dsm), threadIdx.x, row0, col0,
                       A0h, A0l, ns0, B0h, B0l, nullptr, O0, ostride0);
    } else {
        id -= tiles0;
        int row0 = (id / nct1) * 128, col0 = (id % nct1) * 128;
        gemm_tile_body(smem_u32(dsm), threadIdx.x, row0, col0,
                       A1h, A1l, ns1, B1h, B1l, nullptr, O1, ostride1);
    }
}

// ---------------- fused elementwise (float2, sibling pairs, inline hsum) ----------------

// leaf node j at (b, d even): c = sig(z_i)*tanh(z_u); h = sig(z_o)*tanh(c)
__device__ __forceinline__ float2 leaf_node2(int j, int b, int d, float* __restrict__ out) {
    size_t zr = ((size_t)j * B_ + b) * FDP + d;
    float2 zi = *(const float2*)(g_Z + zr);
    float2 zo = *(const float2*)(g_Z + zr + D_);
    float2 zu = *(const float2*)(g_Z + zr + 2 * D_);
    float2 c, h;
    c.x = sigm(zi.x) * tanhf(zu.x);
    c.y = sigm(zi.y) * tanhf(zu.y);
    h.x = sigm(zo.x) * tanhf(c.x);
    h.y = sigm(zo.y) * tanhf(c.y);
    *(float2*)(g_C + ((size_t)j * B_ + b) * D_ + d) = c;
    size_t ro = (size_t)b * N_ + j;
    *(float2*)(out + ro * D_ + d) = h;
    *(uint32_t*)(g_h_hi + ro * AK + d) = pack_bf16_hi2(h.x, h.y);
    *(uint32_t*)(g_h_lo + ro * AK + d) = pack_bf16_lo2(h.x, h.y);
    return h;
}

// internal node j at (b, d even)
__device__ __forceinline__ float2 comb_node2(int j, int b, int d, float* __restrict__ out) {
    size_t zr = ((size_t)j * B_ + b) * FDP + d;
    size_t pj = ((size_t)j * B_ + b) * PIOU_N + d;
    int a = 2 * j + 1, a2 = 2 * j + 2;
    float2 zi = *(const float2*)(g_Z + zr);
    float2 zo = *(const float2*)(g_Z + zr + D_);
    float2 zu = *(const float2*)(g_Z + zr + 2 * D_);
    float2 zf = *(const float2*)(g_Z + zr + 3 * D_);
    float2 pi = *(const float2*)(g_Piou + pj);
    float2 po = *(const float2*)(g_Piou + pj + D_);
    float2 pu = *(const float2*)(g_Piou + pj + 2 * D_);
    float2 fa2 = *(const float2*)(g_Pf + ((size_t)a  * B_ + b) * PF_N + d);
    float2 fb2 = *(const float2*)(g_Pf + ((size_t)a2 * B_ + b) * PF_N + d);
    float2 ca = *(const float2*)(g_C + ((size_t)a  * B_ + b) * D_ + d);
    float2 cb = *(const float2*)(g_C + ((size_t)a2 * B_ + b) * D_ + d);
    float2 c, h;
    {
        float ii = sigm(zi.x + pi.x), oo = sigm(zo.x + po.x), uu = tanhf(zu.x + pu.x);
        float fa = sigm(fa2.x + zf.x), fb = sigm(fb2.x + zf.x);
        c.x = ii * uu + fa * ca.x + fb * cb.x;
        h.x = oo * tanhf(c.x);
    }
    {
        float ii = sigm(zi.y + pi.y), oo = sigm(zo.y + po.y), uu = tanhf(zu.y + pu.y);
        float fa = sigm(fa2.y + zf.y), fb = sigm(fb2.y + zf.y);
        c.y = ii * uu + fa * ca.y + fb * cb.y;
        h.y = oo * tanhf(c.y);
    }
    *(float2*)(g_C + ((size_t)j * B_ + b) * D_ + d) = c;
    size_t ro = (size_t)b * N_ + j;
    *(float2*)(out + ro * D_ + d) = h;
    *(uint32_t*)(g_h_hi + ro * AK + d) = pack_bf16_hi2(h.x, h.y);
    *(uint32_t*)(g_h_lo + ro * AK + d) = pack_bf16_lo2(h.x, h.y);
    return h;
}

__device__ __forceinline__ void store_hs2(int jp, int b, int d, float2 h1, float2 h2) {
    float sx = h1.x + h2.x, sy = h1.y + h2.y;
    size_t ro = (size_t)b * N_ + jp;
    *(uint32_t*)(g_hs_hi + ro * AK + d) = pack_bf16_hi2(sx, sy);
    *(uint32_t*)(g_hs_lo + ro * AK + d) = pack_bf16_lo2(sx, sy);
}

// leaves (63..126) + hs for level-5 parents (31..62). One thread = one sibling pair x (b, d2).
#define D2 (D_ / 2)   // 150
__global__ void leaf_fused_k(float* __restrict__ out) {
    int idx = blockIdx.x * blockDim.x + threadIdx.x;
    const int total = 32 * B_ * D2;
    if (idx >= total) return;
    int d  = (idx % D2) * 2;
    int rb = idx / D2;
    int b  = rb % B_;
    int jp = 31 + rb / B_;                 // level-5 parent
    float2 h1 = leaf_node2(2 * jp + 1, b, d, out);
    float2 h2 = leaf_node2(2 * jp + 2, b, d, out);
    store_hs2(jp, b, d, h1, h2);
}

// internal level pl >= 1: nodes at level pl as sibling pairs of level pl-1 parents; emits hs.
__global__ void comb_fused_k(int pstart, int npar, float* __restrict__ out) {
    int idx = blockIdx.x * blockDim.x + threadIdx.x;
    int total = npar * B_ * D2;
    if (idx >= total) return;
    int d  = (idx % D2) * 2;
    int rb = idx / D2;
    int b  = rb % B_;
    int jp = pstart + rb / B_;             // level pl-1 parent
    float2 h1 = comb_node2(2 * jp + 1, b, d, out);
    float2 h2 = comb_node2(2 * jp + 2, b, d, out);
    store_hs2(jp, b, d, h1, h2);
}

// root (node 0): no hs needed.
__global__ void comb_root_k(float* __restrict__ out) {
    int idx = blockIdx.x * blockDim.x + threadIdx.x;
    const int total = B_ * D2;
    if (idx >= total) return;
    int d = (idx % D2) * 2;
    int b = idx / D2;
    comb_node2(0, b, d, out);
}

extern "C" void kernel_launch(void* const* d_in, const int* in_sizes, int n_in,
                              void* d_out, int out_size) {
    const float* x     = (const float*)d_in[0];
    const float* Wioux = (const float*)d_in[1];
    const float* bioux = (const float*)d_in[2];
    const float* Wiouh = (const float*)d_in[3];
    const float* biouh = (const float*)d_in[4];
    const float* Wfx   = (const float*)d_in[5];
    const float* bfx   = (const float*)d_in[6];
    const float* Wfh   = (const float*)d_in[7];
    const float* bfh   = (const float*)d_in[8];
    float* out = (float*)d_out;

    float *Zp, *Piou, *Pf, *bcp;
    unsigned short *xh, *xl, *hh, *hl, *hsh, *hsl, *wch, *wcl, *wi2h, *wi2l, *wfh2h, *wfh2l;
    cudaGetSymbolAddress((void**)&Zp,    g_Z);
    cudaGetSymbolAddress((void**)&Piou,  g_Piou);
    cudaGetSymbolAddress((void**)&Pf,    g_Pf);
    cudaGetSymbolAddress((void**)&bcp,   g_bc);
    cudaGetSymbolAddress((void**)&xh,    g_x_hi);
    cudaGetSymbolAddress((void**)&xl,    g_x_lo);
    cudaGetSymbolAddress((void**)&hh,    g_h_hi);
    cudaGetSymbolAddress((void**)&hl,    g_h_lo);
    cudaGetSymbolAddress((void**)&hsh,   g_hs_hi);
    cudaGetSymbolAddress((void**)&hsl,   g_hs_lo);
    cudaGetSymbolAddress((void**)&wch,   g_WtC_hi);
    cudaGetSymbolAddress((void**)&wcl,   g_WtC_lo);
    cudaGetSymbolAddress((void**)&wi2h,  g_Wiou2_hi);
    cudaGetSymbolAddress((void**)&wi2l,  g_Wiou2_lo);
    cudaGetSymbolAddress((void**)&wfh2h, g_Wfh2_hi);
    cudaGetSymbolAddress((void**)&wfh2l, g_Wfh2_lo);

    cudaFuncSetAttribute(gemm_m,  cudaFuncAttributeMaxDynamicSharedMemorySize, SMEM_DYN);
    cudaFuncSetAttribute(gemm2_k, cudaFuncAttributeMaxDynamicSharedMemorySize, SMEM_DYN);

    // 1. pack weights (transpose + split) + combined bias
    pack_k<<<(FDP * WK + 255) / 256, 256>>>(Wioux, bioux, Wiouh, biouh, Wfx, bfx, Wfh, bfh);

    // 2. split x into bf16 hi/lo
    xconv_k<<<(N_ * B_ * (AK / 2) + 255) / 256, 256>>>(x);

    // 3. Z = x @ [Wioux|Wfx] + bias, all nodes  (M = 65024, N = 1280)
    {
        dim3 grid(FDP / 128, (N_ * B_) / 128);
        gemm_m<<<grid, GT_THREADS, SMEM_DYN>>>(xh, xl, 0, wch, wcl, bcp, Zp, FDP);
    }

    // 4. leaves (nodes 63..126) + hs for level-5 parents, fused
    leaf_fused_k<<<(32 * B_ * D2 + 255) / 256, 256>>>(out);

    // 5. levels pl = 5 .. 1: merged GEMM, then fused comb (+ hs for pl-1)
    for (int pl = 5; pl >= 1; --pl) {
        int ps = (1 << pl) - 1, np = 1 << pl;             // parent start/count (level pl)
        int cs = (1 << (pl + 1)) - 1, nc = 1 << (pl + 1); // child start/count  (level pl+1)

        int tiles0 = (np * 4) * (PIOU_N / 128);
        int tiles1 = (nc * 4) * (PF_N / 128);
        gemm2_k<<<tiles0 + tiles1, GT_THREADS, SMEM_DYN>>>(
            hsh, hsl, ps, wi2h, wi2l, Piou + (size_t)ps * B_ * PIOU_N, PIOU_N, PIOU_N / 128, tiles0,
            hh,  hl,  cs, wfh2h, wfh2l, Pf  + (size_t)cs * B_ * PF_N,  PF_N,  PF_N / 128);

        // comb for level pl nodes as sibling pairs of level pl-1 parents
        int pps = (1 << (pl - 1)) - 1, npp = 1 << (pl - 1);
        comb_fused_k<<<(npp * B_ * D2 + 255) / 256, 256>>>(pps, npp, out);
    }

    // 6. root: gemm for node 0 (Piou) + children 1,2 (Pf), then root comb
    {
        int tiles0 = 4 * (PIOU_N / 128);   // 32
        int tiles1 = 8 * (PF_N / 128);     // 24
        gemm2_k<<<tiles0 + tiles1, GT_THREADS, SMEM_DYN>>>(
            hsh, hsl, 0, wi2h, wi2l, Piou, PIOU_N, PIOU_N / 128, tiles0,
            hh,  hl,  1, wfh2h, wfh2l, Pf + (size_t)1 * B_ * PF_N, PF_N, PF_N / 128);
        comb_root_k<<<(B_ * D2 + 255) / 256, 256>>>(out);
    }
    (void)in_sizes; (void)n_in; (void)out_size;
}

// round 13
// speedup vs baseline: 1.6968x; 1.2794x over previous
#include <cuda_runtime.h>
#include <cuda_fp16.h>
#include <cstdint>

#define B_  512
#define N_  127
#define D_  300
#define FD  1200    // 4*D : [i | o | u | f]
#define FDP 1280    // padded col stride for Z (10 tiles of 128)
#define PIOU_N 1024 // padded col count for Piou (900 used: [i|o|u] at 0/300/600)
#define PF_N   384  // padded col count for Pf (300 used)
#define AK  320     // padded K stride (10 chunks of 32)
#define WK  320

// ---------------- scratch (static device allocations) ----------------
__device__ float g_Z[(size_t)N_ * B_ * FDP];          // x @ [Wioux|Wfx] + bias
__device__ float g_Piou[(size_t)63 * B_ * PIOU_N];    // hsum @ Wiouh   (parents 0..62)
__device__ float g_Pf[(size_t)N_ * B_ * PF_N];        // h @ Wfh        (children 1..126)
__device__ float g_C[(size_t)N_ * B_ * D_];           // cell states
__device__ unsigned short g_x_hi[(size_t)N_ * B_ * AK];    // fp16 activation splits
__device__ unsigned short g_x_lo[(size_t)N_ * B_ * AK];
__device__ unsigned short g_h_hi[(size_t)N_ * B_ * AK];
__device__ unsigned short g_h_lo[(size_t)N_ * B_ * AK];
__device__ unsigned short g_hs_hi[(size_t)N_ * B_ * AK];   // children h-sum (parents)
__device__ unsigned short g_hs_lo[(size_t)N_ * B_ * AK];
__device__ unsigned short g_WtC[FDP * WK];            // [Wioux|Wfx]^T fp16 (n-major, k-contig)
__device__ unsigned short g_Wiou2[PIOU_N * WK];       // Wiouh^T fp16
__device__ unsigned short g_Wfh2[PF_N * WK];          // Wfh^T fp16
__device__ float g_bc[FDP];                           // combined bias for Z (pads zero)

__device__ __forceinline__ float sigm(float x) { return 1.0f / (1.0f + __expf(-x)); }

__device__ __forceinline__ uint32_t pack_f16_hi2(float x, float y) {
    __half hx = __float2half_rn(x);
    __half hy = __float2half_rn(y);
    return (uint32_t)__half_as_ushort(hx) | ((uint32_t)__half_as_ushort(hy) << 16);
}
__device__ __forceinline__ uint32_t pack_f16_lo2(float x, float y) {
    __half hx = __float2half_rn(x);
    __half hy = __float2half_rn(y);
    __half lx = __float2half_rn(x - __half2float(hx));
    __half ly = __float2half_rn(y - __half2float(hy));
    return (uint32_t)__half_as_ushort(lx) | ((uint32_t)__half_as_ushort(ly) << 16);
}

// ---------------- PTX helpers (sm_80-era; compile on plain sm_103) ----------------
__device__ __forceinline__ uint32_t smem_u32(const void* p) {
    uint32_t a;
    asm("{ .reg .u64 t; cvta.to.shared.u64 t, %1; cvt.u32.u64 %0, t; }" : "=r"(a) : "l"(p));
    return a;
}
__device__ __forceinline__ void cp16(uint32_t dst, const void* src) {
    uint64_t gsrc;
    asm("cvta.to.global.u64 %0, %1;" : "=l"(gsrc) : "l"(src));
    asm volatile("cp.async.cg.shared.global [%0], [%1], 16;" :: "r"(dst), "l"(gsrc));
}
#define CP_COMMIT() asm volatile("cp.async.commit_group;" ::: "memory")
#define CP_WAIT(n)  asm volatile("cp.async.wait_group %0;" :: "n"(n) : "memory")

__device__ __forceinline__ void ldsm4(uint32_t* r, uint32_t addr) {
    asm volatile("ldmatrix.sync.aligned.m8n8.x4.shared.b16 {%0,%1,%2,%3}, [%4];"
                 : "=r"(r[0]), "=r"(r[1]), "=r"(r[2]), "=r"(r[3]) : "r"(addr));
}
__device__ __forceinline__ void mma16816(float* c, const uint32_t* a, uint32_t b0, uint32_t b1) {
    asm volatile(
        "mma.sync.aligned.m16n8k16.row.col.f32.f16.f16.f32 "
        "{%0,%1,%2,%3}, {%4,%5,%6,%7}, {%8,%9}, {%0,%1,%2,%3};"
        : "+f"(c[0]), "+f"(c[1]), "+f"(c[2]), "+f"(c[3])
        : "r"(a[0]), "r"(a[1]), "r"(a[2]), "r"(a[3]), "r"(b0), "r"(b1));
}

// ---------------- pack weights: transpose + fp16 + combined bias ----------------
__global__ void pack_k(const float* __restrict__ Wioux, const float* __restrict__ bioux,
                       const float* __restrict__ Wiouh, const float* __restrict__ biouh,
                       const float* __restrict__ Wfx,  const float* __restrict__ bfx,
                       const float* __restrict__ Wfh,  const float* __restrict__ bfh) {
    int idx = blockIdx.x * blockDim.x + threadIdx.x;
    if (idx >= FDP * WK) return;
    int n = idx / WK, k = idx % WK;

    {
        float wc = 0.0f;
        if (k < D_ && n < FD) {
            wc = (n < 3 * D_) ? Wioux[k * 3 * D_ + n] : Wfx[k * D_ + n - 3 * D_];
        }
        g_WtC[idx] = __half_as_ushort(__float2half_rn(wc));
    }
    if (n < PIOU_N) {
        float w = (k < D_ && n < 3 * D_) ? Wiouh[k * 3 * D_ + n] : 0.0f;
        g_Wiou2[n * WK + k] = __half_as_ushort(__float2half_rn(w));
    }
    if (n < PF_N) {
        float w = (k < D_ && n < D_) ? Wfh[k * D_ + n] : 0.0f;
        g_Wfh2[n * WK + k] = __half_as_ushort(__float2half_rn(w));
    }
    if (idx < FDP)
        g_bc[idx] = (idx >= FD) ? 0.0f
                  : (idx < 3 * D_) ? (bioux[idx] + biouh[idx])
                                   : (bfx[idx - 3 * D_] + bfh[idx - 3 * D_]);
}

// ---------------- convert x (fp32) -> fp16 hi/lo, padded K stride ----------------
__global__ void xconv_k(const float* __restrict__ x) {
    int idx = blockIdx.x * blockDim.x + threadIdx.x;
    const int pairs = AK / 2;                       // 160
    if (idx >= N_ * B_ * pairs) return;
    int r  = idx / pairs;
    int k  = (idx % pairs) * 2;
    if (k >= D_) return;                            // pads stay zero (static init)
    float a0 = x[(size_t)r * D_ + k];
    float a1 = x[(size_t)r * D_ + k + 1];
    *(uint32_t*)(g_x_hi + (size_t)r * AK + k) = pack_f16_hi2(a0, a1);
    *(uint32_t*)(g_x_lo + (size_t)r * AK + k) = pack_f16_lo2(a0, a1);
}

// ---------------- mma.sync fp16 2-term GEMM tile body ----------------
// D = (Ahi + Alo) @ B^T  (exact activation; weight fp16 quantization only).
// Block tile 128x128, K-tile 32, 2-stage cp.async, 8 warps (2m x 4n), 2 CTAs/SM.
#define GT_THREADS 256
#define SROW 40                     // padded smem row (f16 elems) = 80B, conflict-free
#define TILE_B (128 * SROW * 2)     // 10240 bytes per tile
#define STAGE_B (3 * TILE_B)        // Ahi, Alo, B
#define SMEM_DYN (2 * STAGE_B)      // 61440 -> 2 CTAs/SM (regs limit)

__device__ __forceinline__ void gemm_tile_body(
    uint32_t sbase, int t, int row0, int col0,
    const unsigned short* __restrict__ Ahi, const unsigned short* __restrict__ Alo,
    int node_start,
    const unsigned short* __restrict__ Bw,
    const float* __restrict__ bias, float* __restrict__ Out, int ostride)
{
    const int wid = t >> 5, lid = t & 31;
    const int wm = (wid >> 2) * 64;      // warp m offset (0/64)
    const int wn = (wid & 3) * 32;       // warp n offset (0/32/64/96)

    float acc[4][4][4];
#pragma unroll
    for (int i = 0; i < 4; i++)
#pragma unroll
        for (int j = 0; j < 4; j++)
#pragma unroll
            for (int k = 0; k < 4; k++) acc[i][j][k] = 0.0f;

    auto load_stage = [&](int slot, int kt) {
        uint32_t sb = sbase + slot * STAGE_B;
        // A tiles hi+lo: 1024 16B chunks
#pragma unroll
        for (int i = 0; i < 4; ++i) {
            int idx = i * GT_THREADS + t;          // 0..1023
            int buf = idx >> 9;                    // 0=hi 1=lo
            int rem = idx & 511;
            int row = rem >> 2, part = rem & 3;
            int R = row0 + row;
            int j = node_start + (R >> 9);
            int b = R & (B_ - 1);
            const unsigned short* src =
                (buf ? Alo : Ahi) + ((size_t)b * N_ + j) * AK + kt + part * 8;
            cp16(sb + buf * TILE_B + row * (SROW * 2) + part * 16, src);
        }
        // B tile: 512 16B chunks
#pragma unroll
        for (int i = 0; i < 2; ++i) {
            int idx = i * GT_THREADS + t;          // 0..511
            int row = idx >> 2, part = idx & 3;
            const unsigned short* src = Bw + (size_t)(col0 + row) * WK + kt + part * 8;
            cp16(sb + 2 * TILE_B + row * (SROW * 2) + part * 16, src);
        }
    };

    const int lr = lid & 15, lc = (lid >> 4) * 8;
    auto compute_stage = [&](int slot) {
        uint32_t sA = sbase + slot * STAGE_B;
        uint32_t sB = sA + 2 * TILE_B;
#pragma unroll
        for (int ks = 0; ks < 32; ks += 16) {
            uint32_t a_hi[4][4], a_lo[4][4];
#pragma unroll
            for (int mt = 0; mt < 4; ++mt) {
                uint32_t ad = sA + ((wm + mt * 16 + lr) * SROW + ks + lc) * 2;
                ldsm4(a_hi[mt], ad);
                ldsm4(a_lo[mt], ad + TILE_B);
            }
            uint32_t b_f[2][4];
#pragma unroll
            for (int nh = 0; nh < 2; ++nh) {
                uint32_t bd = sB + ((wn + nh * 16 + lr) * SROW + ks + lc) * 2;
                ldsm4(b_f[nh], bd);
            }
#pragma unroll
            for (int mt = 0; mt < 4; ++mt)
#pragma unroll
                for (int nt = 0; nt < 4; ++nt) {
                    uint32_t b0 = b_f[nt >> 1][nt & 1], b1 = b_f[nt >> 1][(nt & 1) + 2];
                    mma16816(acc[mt][nt], a_hi[mt], b0, b1);
                    mma16816(acc[mt][nt], a_lo[mt], b0, b1);
                }
        }
    };

    load_stage(0, 0);
    CP_COMMIT();
#pragma unroll 1
    for (int it = 0; it < 10; ++it) {
        if (it + 1 < 10) {
            load_stage((it + 1) & 1, (it + 1) * 32);
            CP_COMMIT();
            CP_WAIT(1);
        } else {
            CP_WAIT(0);
        }
        __syncthreads();
        compute_stage(it & 1);
        __syncthreads();
    }

    const int g = lid >> 2, i4 = lid & 3;
#pragma unroll
    for (int mt = 0; mt < 4; ++mt) {
        int r0 = row0 + wm + mt * 16 + g;
#pragma unroll
        for (int nt = 0; nt < 4; ++nt) {
            int cc = col0 + wn + nt * 8 + i4 * 2;
            float b0v = 0.0f, b1v = 0.0f;
            if (bias) { b0v = bias[cc]; b1v = bias[cc + 1]; }
            float* o0 = Out + (size_t)r0 * ostride + cc;
            float* o1 = Out + (size_t)(r0 + 8) * ostride + cc;
            o0[0] = acc[mt][nt][0] + b0v;
            o0[1] = acc[mt][nt][1] + b1v;
            o1[0] = acc[mt][nt][2] + b0v;
            o1[1] = acc[mt][nt][3] + b1v;
        }
    }
}

// Z GEMM: blockIdx.x = col tile (L2 A-reuse), blockIdx.y = row tile
__global__ __launch_bounds__(GT_THREADS) void gemm_m(
    const unsigned short* __restrict__ Ahi, const unsigned short* __restrict__ Alo,
    int node_start, const unsigned short* __restrict__ Bw,
    const float* __restrict__ bias, float* __restrict__ Out, int ostride)
{
    extern __shared__ char dsm[];
    gemm_tile_body(smem_u32(dsm), threadIdx.x,
                   blockIdx.y * 128, blockIdx.x * 128,
                   Ahi, Alo, node_start, Bw, bias, Out, ostride);
}

// Merged two-job GEMM (one launch per tree level): flat grid, job0 = Piou, job1 = Pf.
__global__ __launch_bounds__(GT_THREADS) void gemm2_k(
    const unsigned short* __restrict__ A0h, const unsigned short* __restrict__ A0l,
    int ns0, const unsigned short* __restrict__ B0,
    float* __restrict__ O0, int ostride0, int nct0, int tiles0,
    const unsigned short* __restrict__ A1h, const unsigned short* __restrict__ A1l,
    int ns1, const unsigned short* __restrict__ B1,
    float* __restrict__ O1, int ostride1, int nct1)
{
    extern __shared__ char dsm[];
    int id = blockIdx.x;
    if (id < tiles0) {
        int row0 = (id / nct0) * 128, col0 = (id % nct0) * 128;
        gemm_tile_body(smem_u32(dsm), threadIdx.x, row0, col0,
                       A0h, A0l, ns0, B0, nullptr, O0, ostride0);
    } else {
        id -= tiles0;
        int row0 = (id / nct1) * 128, col0 = (id % nct1) * 128;
        gemm_tile_body(smem_u32(dsm), threadIdx.x, row0, col0,
                       A1h, A1l, ns1, B1, nullptr, O1, ostride1);
    }
}

// ---------------- fused elementwise (float2, sibling pairs, inline hsum) ----------------

__device__ __forceinline__ float2 leaf_node2(int j, int b, int d, float* __restrict__ out) {
    size_t zr = ((size_t)j * B_ + b) * FDP + d;
    float2 zi = *(const float2*)(g_Z + zr);
    float2 zo = *(const float2*)(g_Z + zr + D_);
    float2 zu = *(const float2*)(g_Z + zr + 2 * D_);
    float2 c, h;
    c.x = sigm(zi.x) * tanhf(zu.x);
    c.y = sigm(zi.y) * tanhf(zu.y);
    h.x = sigm(zo.x) * tanhf(c.x);
    h.y = sigm(zo.y) * tanhf(c.y);
    *(float2*)(g_C + ((size_t)j * B_ + b) * D_ + d) = c;
    size_t ro = (size_t)b * N_ + j;
    *(float2*)(out + ro * D_ + d) = h;
    *(uint32_t*)(g_h_hi + ro * AK + d) = pack_f16_hi2(h.x, h.y);
    *(uint32_t*)(g_h_lo + ro * AK + d) = pack_f16_lo2(h.x, h.y);
    return h;
}

__device__ __forceinline__ float2 comb_node2(int j, int b, int d, float* __restrict__ out) {
    size_t zr = ((size_t)j * B_ + b) * FDP + d;
    size_t pj = ((size_t)j * B_ + b) * PIOU_N + d;
    int a = 2 * j + 1, a2 = 2 * j + 2;
    float2 zi = *(const float2*)(g_Z + zr);
    float2 zo = *(const float2*)(g_Z + zr + D_);
    float2 zu = *(const float2*)(g_Z + zr + 2 * D_);
    float2 zf = *(const float2*)(g_Z + zr + 3 * D_);
    float2 pi = *(const float2*)(g_Piou + pj);
    float2 po = *(const float2*)(g_Piou + pj + D_);
    float2 pu = *(const float2*)(g_Piou + pj + 2 * D_);
    float2 fa2 = *(const float2*)(g_Pf + ((size_t)a  * B_ + b) * PF_N + d);
    float2 fb2 = *(const float2*)(g_Pf + ((size_t)a2 * B_ + b) * PF_N + d);
    float2 ca = *(const float2*)(g_C + ((size_t)a  * B_ + b) * D_ + d);
    float2 cb = *(const float2*)(g_C + ((size_t)a2 * B_ + b) * D_ + d);
    float2 c, h;
    {
        float ii = sigm(zi.x + pi.x), oo = sigm(zo.x + po.x), uu = tanhf(zu.x + pu.x);
        float fa = sigm(fa2.x + zf.x), fb = sigm(fb2.x + zf.x);
        c.x = ii * uu + fa * ca.x + fb * cb.x;
        h.x = oo * tanhf(c.x);
    }
    {
        float ii = sigm(zi.y + pi.y), oo = sigm(zo.y + po.y), uu = tanhf(zu.y + pu.y);
        float fa = sigm(fa2.y + zf.y), fb = sigm(fb2.y + zf.y);
        c.y = ii * uu + fa * ca.y + fb * cb.y;
        h.y = oo * tanhf(c.y);
    }
    *(float2*)(g_C + ((size_t)j * B_ + b) * D_ + d) = c;
    size_t ro = (size_t)b * N_ + j;
    *(float2*)(out + ro * D_ + d) = h;
    *(uint32_t*)(g_h_hi + ro * AK + d) = pack_f16_hi2(h.x, h.y);
    *(uint32_t*)(g_h_lo + ro * AK + d) = pack_f16_lo2(h.x, h.y);
    return h;
}

__device__ __forceinline__ void store_hs2(int jp, int b, int d, float2 h1, float2 h2) {
    float sx = h1.x + h2.x, sy = h1.y + h2.y;
    size_t ro = (size_t)b * N_ + jp;
    *(uint32_t*)(g_hs_hi + ro * AK + d) = pack_f16_hi2(sx, sy);
    *(uint32_t*)(g_hs_lo + ro * AK + d) = pack_f16_lo2(sx, sy);
}

#define D2 (D_ / 2)   // 150
__global__ void leaf_fused_k(float* __restrict__ out) {
    int idx = blockIdx.x * blockDim.x + threadIdx.x;
    const int total = 32 * B_ * D2;
    if (idx >= total) return;
    int d  = (idx % D2) * 2;
    int rb = idx / D2;
    int b  = rb % B_;
    int jp = 31 + rb / B_;                 // level-5 parent
    float2 h1 = leaf_node2(2 * jp + 1, b, d, out);
    float2 h2 = leaf_node2(2 * jp + 2, b, d, out);
    store_hs2(jp, b, d, h1, h2);
}

__global__ void comb_fused_k(int pstart, int npar, float* __restrict__ out) {
    int idx = blockIdx.x * blockDim.x + threadIdx.x;
    int total = npar * B_ * D2;
    if (idx >= total) return;
    int d  = (idx % D2) * 2;
    int rb = idx / D2;
    int b  = rb % B_;
    int jp = pstart + rb / B_;             // level pl-1 parent
    float2 h1 = comb_node2(2 * jp + 1, b, d, out);
    float2 h2 = comb_node2(2 * jp + 2, b, d, out);
    store_hs2(jp, b, d, h1, h2);
}

__global__ void comb_root_k(float* __restrict__ out) {
    int idx = blockIdx.x * blockDim.x + threadIdx.x;
    const int total = B_ * D2;
    if (idx >= total) return;
    int d = (idx % D2) * 2;
    int b = idx / D2;
    comb_node2(0, b, d, out);
}

extern "C" void kernel_launch(void* const* d_in, const int* in_sizes, int n_in,
                              void* d_out, int out_size) {
    const float* x     = (const float*)d_in[0];
    const float* Wioux = (const float*)d_in[1];
    const float* bioux = (const float*)d_in[2];
    const float* Wiouh = (const float*)d_in[3];
    const float* biouh = (const float*)d_in[4];
    const float* Wfx   = (const float*)d_in[5];
    const float* bfx   = (const float*)d_in[6];
    const float* Wfh   = (const float*)d_in[7];
    const float* bfh   = (const float*)d_in[8];
    float* out = (float*)d_out;

    float *Zp, *Piou, *Pf, *bcp;
    unsigned short *xh, *xl, *hh, *hl, *hsh, *hsl, *wc, *wi2, *wfh2;
    cudaGetSymbolAddress((void**)&Zp,   g_Z);
    cudaGetSymbolAddress((void**)&Piou, g_Piou);
    cudaGetSymbolAddress((void**)&Pf,   g_Pf);
    cudaGetSymbolAddress((void**)&bcp,  g_bc);
    cudaGetSymbolAddress((void**)&xh,   g_x_hi);
    cudaGetSymbolAddress((void**)&xl,   g_x_lo);
    cudaGetSymbolAddress((void**)&hh,   g_h_hi);
    cudaGetSymbolAddress((void**)&hl,   g_h_lo);
    cudaGetSymbolAddress((void**)&hsh,  g_hs_hi);
    cudaGetSymbolAddress((void**)&hsl,  g_hs_lo);
    cudaGetSymbolAddress((void**)&wc,   g_WtC);
    cudaGetSymbolAddress((void**)&wi2,  g_Wiou2);
    cudaGetSymbolAddress((void**)&wfh2, g_Wfh2);

    cudaFuncSetAttribute(gemm_m,  cudaFuncAttributeMaxDynamicSharedMemorySize, SMEM_DYN);
    cudaFuncSetAttribute(gemm2_k, cudaFuncAttributeMaxDynamicSharedMemorySize, SMEM_DYN);

    // 1. pack weights (transpose + fp16) + combined bias
    pack_k<<<(FDP * WK + 255) / 256, 256>>>(Wioux, bioux, Wiouh, biouh, Wfx, bfx, Wfh, bfh);

    // 2. split x into fp16 hi/lo
    xconv_k<<<(N_ * B_ * (AK / 2) + 255) / 256, 256>>>(x);

    // 3. Z = x @ [Wioux|Wfx] + bias, all nodes  (M = 65024, N = 1280)
    {
        dim3 grid(FDP / 128, (N_ * B_) / 128);
        gemm_m<<<grid, GT_THREADS, SMEM_DYN>>>(xh, xl, 0, wc, bcp, Zp, FDP);
    }

    // 4. leaves (nodes 63..126) + hs for level-5 parents, fused
    leaf_fused_k<<<(32 * B_ * D2 + 255) / 256, 256>>>(out);

    // 5. levels pl = 5 .. 1: merged GEMM, then fused comb (+ hs for pl-1)
    for (int pl = 5; pl >= 1; --pl) {
        int ps = (1 << pl) - 1, np = 1 << pl;             // parent start/count (level pl)
        int cs = (1 << (pl + 1)) - 1, nc = 1 << (pl + 1); // child start/count  (level pl+1)

        int tiles0 = (np * 4) * (PIOU_N / 128);
        int tiles1 = (nc * 4) * (PF_N / 128);
        gemm2_k<<<tiles0 + tiles1, GT_THREADS, SMEM_DYN>>>(
            hsh, hsl, ps, wi2, Piou + (size_t)ps * B_ * PIOU_N, PIOU_N, PIOU_N / 128, tiles0,
            hh,  hl,  cs, wfh2, Pf  + (size_t)cs * B_ * PF_N,  PF_N,  PF_N / 128);

        int pps = (1 << (pl - 1)) - 1, npp = 1 << (pl - 1);
        comb_fused_k<<<(npp * B_ * D2 + 255) / 256, 256>>>(pps, npp, out);
    }

    // 6. root: gemm for node 0 (Piou) + children 1,2 (Pf), then root comb
    {
        int tiles0 = 4 * (PIOU_N / 128);   // 32
        int tiles1 = 8 * (PF_N / 128);     // 24
        gemm2_k<<<tiles0 + tiles1, GT_THREADS, SMEM_DYN>>>(
            hsh, hsl, 0, wi2, Piou, PIOU_N, PIOU_N / 128, tiles0,
            hh,  hl,  1, wfh2, Pf + (size_t)1 * B_ * PF_N, PF_N, PF_N / 128);
        comb_root_k<<<(B_ * D2 + 255) / 256, 256>>>(out);
    }
    (void)in_sizes; (void)n_in; (void)out_size;
}

// round 16
// speedup vs baseline: 2.3342x; 1.3757x over previous
#include <cuda_runtime.h>
#include <cuda_fp16.h>
#include <cstdint>

#define B_  512
#define N_  127
#define D_  300
#define FD  1200    // 4*D : [i | o | u | f]
#define FDP 1280    // padded col stride for Z (10 tiles of 128)
#define PIOU_N 1024 // padded col count for Piou (900 used: [i|o|u] at 0/300/600)
#define PF_N   384  // padded col count for Pf (300 used)
#define AK  320     // padded K stride (10 chunks of 32)
#define WK  320

// ---------------- scratch (static device allocations) ----------------
__device__ float g_Z[(size_t)N_ * B_ * FDP];          // x @ [Wioux|Wfx] + bias
__device__ float g_Piou[(size_t)63 * B_ * PIOU_N];    // hsum @ Wiouh   (parents 0..62)
__device__ float g_Pf[(size_t)N_ * B_ * PF_N];        // h @ Wfh        (children 1..126)
__device__ float g_C[(size_t)N_ * B_ * D_];           // cell states
__device__ unsigned short g_x16[(size_t)N_ * B_ * AK];    // fp16 activations
__device__ unsigned short g_h16[(size_t)N_ * B_ * AK];
__device__ unsigned short g_hs16[(size_t)N_ * B_ * AK];   // children h-sum (parents)
__device__ unsigned short g_WtC[FDP * WK];            // [Wioux|Wfx]^T fp16 (n-major, k-contig)
__device__ unsigned short g_Wiou2[PIOU_N * WK];       // Wiouh^T fp16
__device__ unsigned short g_Wfh2[PF_N * WK];          // Wfh^T fp16
__device__ float g_bc[FDP];                           // combined bias for Z (pads zero)

__device__ __forceinline__ float sigm(float x) { return 1.0f / (1.0f + __expf(-x)); }

__device__ __forceinline__ uint32_t pack_f16_2(float x, float y) {
    __half hx = __float2half_rn(x);
    __half hy = __float2half_rn(y);
    return (uint32_t)__half_as_ushort(hx) | ((uint32_t)__half_as_ushort(hy) << 16);
}

// ---------------- PTX helpers (sm_80-era; compile on plain sm_103) ----------------
__device__ __forceinline__ uint32_t smem_u32(const void* p) {
    uint32_t a;
    asm("{ .reg .u64 t; cvta.to.shared.u64 t, %1; cvt.u32.u64 %0, t; }" : "=r"(a) : "l"(p));
    return a;
}
__device__ __forceinline__ void cp16(uint32_t dst, const void* src) {
    uint64_t gsrc;
    asm("cvta.to.global.u64 %0, %1;" : "=l"(gsrc) : "l"(src));
    asm volatile("cp.async.cg.shared.global [%0], [%1], 16;" :: "r"(dst), "l"(gsrc));
}
#define CP_COMMIT() asm volatile("cp.async.commit_group;" ::: "memory")
#define CP_WAIT(n)  asm volatile("cp.async.wait_group %0;" :: "n"(n) : "memory")

__device__ __forceinline__ void ldsm4(uint32_t* r, uint32_t addr) {
    asm volatile("ldmatrix.sync.aligned.m8n8.x4.shared.b16 {%0,%1,%2,%3}, [%4];"
                 : "=r"(r[0]), "=r"(r[1]), "=r"(r[2]), "=r"(r[3]) : "r"(addr));
}
__device__ __forceinline__ void mma16816(float* c, const uint32_t* a, uint32_t b0, uint32_t b1) {
    asm volatile(
        "mma.sync.aligned.m16n8k16.row.col.f32.f16.f16.f32 "
        "{%0,%1,%2,%3}, {%4,%5,%6,%7}, {%8,%9}, {%0,%1,%2,%3};"
        : "+f"(c[0]), "+f"(c[1]), "+f"(c[2]), "+f"(c[3])
        : "r"(a[0]), "r"(a[1]), "r"(a[2]), "r"(a[3]), "r"(b0), "r"(b1));
}

// ---------------- pack weights: transpose + fp16 + combined bias ----------------
__global__ void pack_k(const float* __restrict__ Wioux, const float* __restrict__ bioux,
                       const float* __restrict__ Wiouh, const float* __restrict__ biouh,
                       const float* __restrict__ Wfx,  const float* __restrict__ bfx,
                       const float* __restrict__ Wfh,  const float* __restrict__ bfh) {
    int idx = blockIdx.x * blockDim.x + threadIdx.x;
    if (idx >= FDP * WK) return;
    int n = idx / WK, k = idx % WK;

    {
        float wc = 0.0f;
        if (k < D_ && n < FD) {
            wc = (n < 3 * D_) ? Wioux[k * 3 * D_ + n] : Wfx[k * D_ + n - 3 * D_];
        }
        g_WtC[idx] = __half_as_ushort(__float2half_rn(wc));
    }
    if (n < PIOU_N) {
        float w = (k < D_ && n < 3 * D_) ? Wiouh[k * 3 * D_ + n] : 0.0f;
        g_Wiou2[n * WK + k] = __half_as_ushort(__float2half_rn(w));
    }
    if (n < PF_N) {
        float w = (k < D_ && n < D_) ? Wfh[k * D_ + n] : 0.0f;
        g_Wfh2[n * WK + k] = __half_as_ushort(__float2half_rn(w));
    }
    if (idx < FDP)
        g_bc[idx] = (idx >= FD) ? 0.0f
                  : (idx < 3 * D_) ? (bioux[idx] + biouh[idx])
                                   : (bfx[idx - 3 * D_] + bfh[idx - 3 * D_]);
}

// ---------------- convert x (fp32) -> fp16, padded K stride ----------------
__global__ void xconv_k(const float* __restrict__ x) {
    int idx = blockIdx.x * blockDim.x + threadIdx.x;
    const int pairs = AK / 2;                       // 160
    if (idx >= N_ * B_ * pairs) return;
    int r  = idx / pairs;
    int k  = (idx % pairs) * 2;
    if (k >= D_) return;                            // pads stay zero (static init)
    float a0 = x[(size_t)r * D_ + k];
    float a1 = x[(size_t)r * D_ + k + 1];
    *(uint32_t*)(g_x16 + (size_t)r * AK + k) = pack_f16_2(a0, a1);
}

// ---------------- mma.sync fp16 1-term GEMM tile body ----------------
// Block tile 128x128, K-tile 32, 2-stage cp.async, 8 warps (2m x 4n).
#define GT_THREADS 256
#define SROW 40                     // padded smem row (f16 elems) = 80B, conflict-free
#define TILE_B (128 * SROW * 2)     // 10240 bytes per tile
#define STAGE_B (2 * TILE_B)        // A, B
#define SMEM_DYN (2 * STAGE_B)      // 40960

__device__ __forceinline__ void gemm_tile_body(
    uint32_t sbase, int t, int row0, int col0,
    const unsigned short* __restrict__ Aw, int node_start,
    const unsigned short* __restrict__ Bw,
    const float* __restrict__ bias, float* __restrict__ Out, int ostride)
{
    const int wid = t >> 5, lid = t & 31;
    const int wm = (wid >> 2) * 64;      // warp m offset (0/64)
    const int wn = (wid & 3) * 32;       // warp n offset (0/32/64/96)

    float acc[4][4][4];
#pragma unroll
    for (int i = 0; i < 4; i++)
#pragma unroll
        for (int j = 0; j < 4; j++)
#pragma unroll
            for (int k = 0; k < 4; k++) acc[i][j][k] = 0.0f;

    auto load_stage = [&](int slot, int kt) {
        uint32_t sb = sbase + slot * STAGE_B;
        // A tile: 512 16B chunks
#pragma unroll
        for (int i = 0; i < 2; ++i) {
            int idx = i * GT_THREADS + t;          // 0..511
            int row = idx >> 2, part = idx & 3;
            int R = row0 + row;
            int j = node_start + (R >> 9);
            int b = R & (B_ - 1);
            const unsigned short* src = Aw + ((size_t)b * N_ + j) * AK + kt + part * 8;
            cp16(sb + row * (SROW * 2) + part * 16, src);
        }
        // B tile: 512 16B chunks
#pragma unroll
        for (int i = 0; i < 2; ++i) {
            int idx = i * GT_THREADS + t;          // 0..511
            int row = idx >> 2, part = idx & 3;
            const unsigned short* src = Bw + (size_t)(col0 + row) * WK + kt + part * 8;
            cp16(sb + TILE_B + row * (SROW * 2) + part * 16, src);
        }
    };

    const int lr = lid & 15, lc = (lid >> 4) * 8;
    auto compute_stage = [&](int slot) {
        uint32_t sA = sbase + slot * STAGE_B;
        uint32_t sB = sA + TILE_B;
#pragma unroll
        for (int ks = 0; ks < 32; ks += 16) {
            uint32_t a_f[4][4];
#pragma unroll
            for (int mt = 0; mt < 4; ++mt) {
                uint32_t ad = sA + ((wm + mt * 16 + lr) * SROW + ks + lc) * 2;
                ldsm4(a_f[mt], ad);
            }
            uint32_t b_f[2][4];
#pragma unroll
            for (int nh = 0; nh < 2; ++nh) {
                uint32_t bd = sB + ((wn + nh * 16 + lr) * SROW + ks + lc) * 2;
                ldsm4(b_f[nh], bd);
            }
#pragma unroll
            for (int mt = 0; mt < 4; ++mt)
#pragma unroll
                for (int nt = 0; nt < 4; ++nt) {
                    uint32_t b0 = b_f[nt >> 1][nt & 1], b1 = b_f[nt >> 1][(nt & 1) + 2];
                    mma16816(acc[mt][nt], a_f[mt], b0, b1);
                }
        }
    };

    load_stage(0, 0);
    CP_COMMIT();
#pragma unroll 1
    for (int it = 0; it < 10; ++it) {
        if (it + 1 < 10) {
            load_stage((it + 1) & 1, (it + 1) * 32);
            CP_COMMIT();
            CP_WAIT(1);
        } else {
            CP_WAIT(0);
        }
        __syncthreads();
        compute_stage(it & 1);
        __syncthreads();
    }

    const int g = lid >> 2, i4 = lid & 3;
#pragma unroll
    for (int mt = 0; mt < 4; ++mt) {
        int r0 = row0 + wm + mt * 16 + g;
#pragma unroll
        for (int nt = 0; nt < 4; ++nt) {
            int cc = col0 + wn + nt * 8 + i4 * 2;
            float b0v = 0.0f, b1v = 0.0f;
            if (bias) { b0v = bias[cc]; b1v = bias[cc + 1]; }
            float* o0 = Out + (size_t)r0 * ostride + cc;
            float* o1 = Out + (size_t)(r0 + 8) * ostride + cc;
            o0[0] = acc[mt][nt][0] + b0v;
            o0[1] = acc[mt][nt][1] + b1v;
            o1[0] = acc[mt][nt][2] + b0v;
            o1[1] = acc[mt][nt][3] + b1v;
        }
    }
}

// Z GEMM: blockIdx.x = col tile (L2 A-reuse), blockIdx.y = row tile
__global__ __launch_bounds__(GT_THREADS) void gemm_m(
    const unsigned short* __restrict__ Aw, int node_start,
    const unsigned short* __restrict__ Bw,
    const float* __restrict__ bias, float* __restrict__ Out, int ostride)
{
    extern __shared__ char dsm[];
    gemm_tile_body(smem_u32(dsm), threadIdx.x,
                   blockIdx.y * 128, blockIdx.x * 128,
                   Aw, node_start, Bw, bias, Out, ostride);
}

// Merged two-job GEMM (one launch per tree level): flat grid, job0 = Piou, job1 = Pf.
__global__ __launch_bounds__(GT_THREADS) void gemm2_k(
    const unsigned short* __restrict__ A0, int ns0, const unsigned short* __restrict__ B0,
    float* __restrict__ O0, int ostride0, int nct0, int tiles0,
    const unsigned short* __restrict__ A1, int ns1, const unsigned short* __restrict__ B1,
    float* __restrict__ O1, int ostride1, int nct1)
{
    extern __shared__ char dsm[];
    int id = blockIdx.x;
    if (id < tiles0) {
        int row0 = (id / nct0) * 128, col0 = (id % nct0) * 128;
        gemm_tile_body(smem_u32(dsm), threadIdx.x, row0, col0,
                       A0, ns0, B0, nullptr, O0, ostride0);
    } else {
        id -= tiles0;
        int row0 = (id / nct1) * 128, col0 = (id % nct1) * 128;
        gemm_tile_body(smem_u32(dsm), threadIdx.x, row0, col0,
                       A1, ns1, B1, nullptr, O1, ostride1);
    }
}

// ---------------- fused elementwise (float2, sibling pairs, inline hsum) ----------------

__device__ __forceinline__ float2 leaf_node2(int j, int b, int d, float* __restrict__ out) {
    size_t zr = ((size_t)j * B_ + b) * FDP + d;
    float2 zi = *(const float2*)(g_Z + zr);
    float2 zo = *(const float2*)(g_Z + zr + D_);
    float2 zu = *(const float2*)(g_Z + zr + 2 * D_);
    float2 c, h;
    c.x = sigm(zi.x) * tanhf(zu.x);
    c.y = sigm(zi.y) * tanhf(zu.y);
    h.x = sigm(zo.x) * tanhf(c.x);
    h.y = sigm(zo.y) * tanhf(c.y);
    *(float2*)(g_C + ((size_t)j * B_ + b) * D_ + d) = c;
    size_t ro = (size_t)b * N_ + j;
    *(float2*)(out + ro * D_ + d) = h;
    *(uint32_t*)(g_h16 + ro * AK + d) = pack_f16_2(h.x, h.y);
    return h;
}

__device__ __forceinline__ float2 comb_node2(int j, int b, int d, float* __restrict__ out) {
    size_t zr = ((size_t)j * B_ + b) * FDP + d;
    size_t pj = ((size_t)j * B_ + b) * PIOU_N + d;
    int a = 2 * j + 1, a2 = 2 * j + 2;
    float2 zi = *(const float2*)(g_Z + zr);
    float2 zo = *(const float2*)(g_Z + zr + D_);
    float2 zu = *(const float2*)(g_Z + zr + 2 * D_);
    float2 zf = *(const float2*)(g_Z + zr + 3 * D_);
    float2 pi = *(const float2*)(g_Piou + pj);
    float2 po = *(const float2*)(g_Piou + pj + D_);
    float2 pu = *(const float2*)(g_Piou + pj + 2 * D_);
    float2 fa2 = *(const float2*)(g_Pf + ((size_t)a  * B_ + b) * PF_N + d);
    float2 fb2 = *(const float2*)(g_Pf + ((size_t)a2 * B_ + b) * PF_N + d);
    float2 ca = *(const float2*)(g_C + ((size_t)a  * B_ + b) * D_ + d);
    float2 cb = *(const float2*)(g_C + ((size_t)a2 * B_ + b) * D_ + d);
    float2 c, h;
    {
        float ii = sigm(zi.x + pi.x), oo = sigm(zo.x + po.x), uu = tanhf(zu.x + pu.x);
        float fa = sigm(fa2.x + zf.x), fb = sigm(fb2.x + zf.x);
        c.x = ii * uu + fa * ca.x + fb * cb.x;
        h.x = oo * tanhf(c.x);
    }
    {
        float ii = sigm(zi.y + pi.y), oo = sigm(zo.y + po.y), uu = tanhf(zu.y + pu.y);
        float fa = sigm(fa2.y + zf.y), fb = sigm(fb2.y + zf.y);
        c.y = ii * uu + fa * ca.y + fb * cb.y;
        h.y = oo * tanhf(c.y);
    }
    *(float2*)(g_C + ((size_t)j * B_ + b) * D_ + d) = c;
    size_t ro = (size_t)b * N_ + j;
    *(float2*)(out + ro * D_ + d) = h;
    *(uint32_t*)(g_h16 + ro * AK + d) = pack_f16_2(h.x, h.y);
    return h;
}

__device__ __forceinline__ void store_hs2(int jp, int b, int d, float2 h1, float2 h2) {
    float sx = h1.x + h2.x, sy = h1.y + h2.y;
    size_t ro = (size_t)b * N_ + jp;
    *(uint32_t*)(g_hs16 + ro * AK + d) = pack_f16_2(sx, sy);
}

#define D2 (D_ / 2)   // 150
__global__ void leaf_fused_k(float* __restrict__ out) {
    int idx = blockIdx.x * blockDim.x + threadIdx.x;
    const int total = 32 * B_ * D2;
    if (idx >= total) return;
    int d  = (idx % D2) * 2;
    int rb = idx / D2;
    int b  = rb % B_;
    int jp = 31 + rb / B_;                 // level-5 parent
    float2 h1 = leaf_node2(2 * jp + 1, b, d, out);
    float2 h2 = leaf_node2(2 * jp + 2, b, d, out);
    store_hs2(jp, b, d, h1, h2);
}

__global__ void comb_fused_k(int pstart, int npar, float* __restrict__ out) {
    int idx = blockIdx.x * blockDim.x + threadIdx.x;
    int total = npar * B_ * D2;
    if (idx >= total) return;
    int d  = (idx % D2) * 2;
    int rb = idx / D2;
    int b  = rb % B_;
    int jp = pstart + rb / B_;             // level pl-1 parent
    float2 h1 = comb_node2(2 * jp + 1, b, d, out);
    float2 h2 = comb_node2(2 * jp + 2, b, d, out);
    store_hs2(jp, b, d, h1, h2);
}

__global__ void comb_root_k(float* __restrict__ out) {
    int idx = blockIdx.x * blockDim.x + threadIdx.x;
    const int total = B_ * D2;
    if (idx >= total) return;
    int d = (idx % D2) * 2;
    int b = idx / D2;
    comb_node2(0, b, d, out);
}

extern "C" void kernel_launch(void* const* d_in, const int* in_sizes, int n_in,
                              void* d_out, int out_size) {
    const float* x     = (const float*)d_in[0];
    const float* Wioux = (const float*)d_in[1];
    const float* bioux = (const float*)d_in[2];
    const float* Wiouh = (const float*)d_in[3];
    const float* biouh = (const float*)d_in[4];
    const float* Wfx   = (const float*)d_in[5];
    const float* bfx   = (const float*)d_in[6];
    const float* Wfh   = (const float*)d_in[7];
    const float* bfh   = (const float*)d_in[8];
    float* out = (float*)d_out;

    float *Zp, *Piou, *Pf, *bcp;
    unsigned short *x16, *h16, *hs16, *wc, *wi2, *wfh2;
    cudaGetSymbolAddress((void**)&Zp,   g_Z);
    cudaGetSymbolAddress((void**)&Piou, g_Piou);
    cudaGetSymbolAddress((void**)&Pf,   g_Pf);
    cudaGetSymbolAddress((void**)&bcp,  g_bc);
    cudaGetSymbolAddress((void**)&x16,  g_x16);
    cudaGetSymbolAddress((void**)&h16,  g_h16);
    cudaGetSymbolAddress((void**)&hs16, g_hs16);
    cudaGetSymbolAddress((void**)&wc,   g_WtC);
    cudaGetSymbolAddress((void**)&wi2,  g_Wiou2);
    cudaGetSymbolAddress((void**)&wfh2, g_Wfh2);

    cudaFuncSetAttribute(gemm_m,  cudaFuncAttributeMaxDynamicSharedMemorySize, SMEM_DYN);
    cudaFuncSetAttribute(gemm2_k, cudaFuncAttributeMaxDynamicSharedMemorySize, SMEM_DYN);

    // 1. pack weights (transpose + fp16) + combined bias
    pack_k<<<(FDP * WK + 255) / 256, 256>>>(Wioux, bioux, Wiouh, biouh, Wfx, bfx, Wfh, bfh);

    // 2. convert x to fp16
    xconv_k<<<(N_ * B_ * (AK / 2) + 255) / 256, 256>>>(x);

    // 3. Z = x @ [Wioux|Wfx] + bias, all nodes  (M = 65024, N = 1280)
    {
        dim3 grid(FDP / 128, (N_ * B_) / 128);
        gemm_m<<<grid, GT_THREADS, SMEM_DYN>>>(x16, 0, wc, bcp, Zp, FDP);
    }

    // 4. leaves (nodes 63..126) + hs for level-5 parents, fused
    leaf_fused_k<<<(32 * B_ * D2 + 255) / 256, 256>>>(out);

    // 5. levels pl = 5 .. 1: merged GEMM, then fused comb (+ hs for pl-1)
    for (int pl = 5; pl >= 1; --pl) {
        int ps = (1 << pl) - 1, np = 1 << pl;             // parent start/count (level pl)
        int cs = (1 << (pl + 1)) - 1, nc = 1 << (pl + 1); // child start/count  (level pl+1)

        int tiles0 = (np * 4) * (PIOU_N / 128);
        int tiles1 = (nc * 4) * (PF_N / 128);
        gemm2_k<<<tiles0 + tiles1, GT_THREADS, SMEM_DYN>>>(
            hs16, ps, wi2, Piou + (size_t)ps * B_ * PIOU_N, PIOU_N, PIOU_N / 128, tiles0,
            h16,  cs, wfh2, Pf  + (size_t)cs * B_ * PF_N,  PF_N,  PF_N / 128);

        int pps = (1 << (pl - 1)) - 1, npp = 1 << (pl - 1);
        comb_fused_k<<<(npp * B_ * D2 + 255) / 256, 256>>>(pps, npp, out);
    }

    // 6. root: gemm for node 0 (Piou) + children 1,2 (Pf), then root comb
    {
        int tiles0 = 4 * (PIOU_N / 128);   // 32
        int tiles1 = 8 * (PF_N / 128);     // 24
        gemm2_k<<<tiles0 + tiles1, GT_THREADS, SMEM_DYN>>>(
            hs16, 0, wi2, Piou, PIOU_N, PIOU_N / 128, tiles0,
            h16,  1, wfh2, Pf + (size_t)1 * B_ * PF_N, PF_N, PF_N / 128);
        comb_root_k<<<(B_ * D2 + 255) / 256, 256>>>(out);
    }
    (void)in_sizes; (void)n_in; (void)out_size;
}

// round 17
// speedup vs baseline: 2.6906x; 1.1527x over previous
#include <cuda_runtime.h>
#include <cuda_fp16.h>
#include <cstdint>

#define B_  512
#define N_  127
#define D_  300
#define FD  1200    // 4*D : [i | o | u | f]
#define FDP 1280    // padded col stride for Z (10 tiles of 128)
#define PIOU_N 1024 // padded col count for Piou (900 used: [i|o|u] at 0/300/600)
#define PF_N   384  // padded col count for Pf (300 used)
#define AK  320     // padded K stride (10 chunks of 32)
#define WK  320

// ---------------- scratch (static device allocations) ----------------
__device__ unsigned short g_Z[(size_t)N_ * B_ * FDP];       // fp16: x @ [Wioux|Wfx] + bias
__device__ unsigned short g_Piou[(size_t)63 * B_ * PIOU_N]; // fp16: hsum @ Wiouh
__device__ unsigned short g_Pf[(size_t)N_ * B_ * PF_N];     // fp16: h @ Wfh
__device__ float g_C[(size_t)N_ * B_ * D_];                 // cell states (fp32)
__device__ unsigned short g_x16[(size_t)N_ * B_ * AK];      // fp16 activations
__device__ unsigned short g_h16[(size_t)N_ * B_ * AK];
__device__ unsigned short g_hs16[(size_t)N_ * B_ * AK];     // children h-sum (parents)
__device__ unsigned short g_WtC[FDP * WK];                  // [Wioux|Wfx]^T fp16
__device__ unsigned short g_Wiou2[PIOU_N * WK];             // Wiouh^T fp16
__device__ unsigned short g_Wfh2[PF_N * WK];                // Wfh^T fp16
__device__ float g_bc[FDP];                                 // combined bias for Z (pads zero)

__device__ __forceinline__ float sigm(float x) { return 1.0f / (1.0f + __expf(-x)); }

__device__ __forceinline__ uint32_t pack_f16_2(float x, float y) {
    __half hx = __float2half_rn(x);
    __half hy = __float2half_rn(y);
    return (uint32_t)__half_as_ushort(hx) | ((uint32_t)__half_as_ushort(hy) << 16);
}
__device__ __forceinline__ float2 ldh2(const unsigned short* p) {
    uint32_t v = *(const uint32_t*)p;
    __half2 h = *(__half2*)&v;
    return __half22float2(h);
}

// ---------------- PTX helpers (sm_80-era; compile on plain sm_103) ----------------
__device__ __forceinline__ uint32_t smem_u32(const void* p) {
    uint32_t a;
    asm("{ .reg .u64 t; cvta.to.shared.u64 t, %1; cvt.u32.u64 %0, t; }" : "=r"(a) : "l"(p));
    return a;
}
__device__ __forceinline__ void cp16(uint32_t dst, const void* src) {
    uint64_t gsrc;
    asm("cvta.to.global.u64 %0, %1;" : "=l"(gsrc) : "l"(src));
    asm volatile("cp.async.cg.shared.global [%0], [%1], 16;" :: "r"(dst), "l"(gsrc));
}
#define CP_COMMIT() asm volatile("cp.async.commit_group;" ::: "memory")
#define CP_WAIT(n)  asm volatile("cp.async.wait_group %0;" :: "n"(n) : "memory")

__device__ __forceinline__ void ldsm4(uint32_t* r, uint32_t addr) {
    asm volatile("ldmatrix.sync.aligned.m8n8.x4.shared.b16 {%0,%1,%2,%3}, [%4];"
                 : "=r"(r[0]), "=r"(r[1]), "=r"(r[2]), "=r"(r[3]) : "r"(addr));
}
__device__ __forceinline__ void mma16816(float* c, const uint32_t* a, uint32_t b0, uint32_t b1) {
    asm volatile(
        "mma.sync.aligned.m16n8k16.row.col.f32.f16.f16.f32 "
        "{%0,%1,%2,%3}, {%4,%5,%6,%7}, {%8,%9}, {%0,%1,%2,%3};"
        : "+f"(c[0]), "+f"(c[1]), "+f"(c[2]), "+f"(c[3])
        : "r"(a[0]), "r"(a[1]), "r"(a[2]), "r"(a[3]), "r"(b0), "r"(b1));
}

// ---------------- pack weights: transpose + fp16 + combined bias ----------------
__global__ void pack_k(const float* __restrict__ Wioux, const float* __restrict__ bioux,
                       const float* __restrict__ Wiouh, const float* __restrict__ biouh,
                       const float* __restrict__ Wfx,  const float* __restrict__ bfx,
                       const float* __restrict__ Wfh,  const float* __restrict__ bfh) {
    int idx = blockIdx.x * blockDim.x + threadIdx.x;
    if (idx >= FDP * WK) return;
    int n = idx / WK, k = idx % WK;

    {
        float wc = 0.0f;
        if (k < D_ && n < FD) {
            wc = (n < 3 * D_) ? Wioux[k * 3 * D_ + n] : Wfx[k * D_ + n - 3 * D_];
        }
        g_WtC[idx] = __half_as_ushort(__float2half_rn(wc));
    }
    if (n < PIOU_N) {
        float w = (k < D_ && n < 3 * D_) ? Wiouh[k * 3 * D_ + n] : 0.0f;
        g_Wiou2[n * WK + k] = __half_as_ushort(__float2half_rn(w));
    }
    if (n < PF_N) {
        float w = (k < D_ && n < D_) ? Wfh[k * D_ + n] : 0.0f;
        g_Wfh2[n * WK + k] = __half_as_ushort(__float2half_rn(w));
    }
    if (idx < FDP)
        g_bc[idx] = (idx >= FD) ? 0.0f
                  : (idx < 3 * D_) ? (bioux[idx] + biouh[idx])
                                   : (bfx[idx - 3 * D_] + bfh[idx - 3 * D_]);
}

// ---------------- convert x (fp32) -> fp16, padded K stride ----------------
__global__ void xconv_k(const float* __restrict__ x) {
    int idx = blockIdx.x * blockDim.x + threadIdx.x;
    const int pairs = AK / 2;                       // 160
    if (idx >= N_ * B_ * pairs) return;
    int r  = idx / pairs;
    int k  = (idx % pairs) * 2;
    if (k >= D_) return;                            // pads stay zero (static init)
    float a0 = x[(size_t)r * D_ + k];
    float a1 = x[(size_t)r * D_ + k + 1];
    *(uint32_t*)(g_x16 + (size_t)r * AK + k) = pack_f16_2(a0, a1);
}

// ---------------- mma.sync fp16 1-term GEMM tile body (fp16 output) ----------------
// Block tile 128x128, K-tile 32, 2-stage cp.async, 8 warps (2m x 4n).
#define GT_THREADS 256
#define SROW 40                     // padded smem row (f16 elems) = 80B, conflict-free
#define TILE_B (128 * SROW * 2)     // 10240 bytes per tile
#define STAGE_B (2 * TILE_B)        // A, B
#define SMEM_DYN (2 * STAGE_B)      // 40960

__device__ __forceinline__ void gemm_tile_body(
    uint32_t sbase, int t, int row0, int col0,
    const unsigned short* __restrict__ Aw, int node_start,
    const unsigned short* __restrict__ Bw,
    const float* __restrict__ bias, unsigned short* __restrict__ Out, int ostride)
{
    const int wid = t >> 5, lid = t & 31;
    const int wm = (wid >> 2) * 64;      // warp m offset (0/64)
    const int wn = (wid & 3) * 32;       // warp n offset (0/32/64/96)

    float acc[4][4][4];
#pragma unroll
    for (int i = 0; i < 4; i++)
#pragma unroll
        for (int j = 0; j < 4; j++)
#pragma unroll
            for (int k = 0; k < 4; k++) acc[i][j][k] = 0.0f;

    auto load_stage = [&](int slot, int kt) {
        uint32_t sb = sbase + slot * STAGE_B;
        // A tile: 512 16B chunks
#pragma unroll
        for (int i = 0; i < 2; ++i) {
            int idx = i * GT_THREADS + t;          // 0..511
            int row = idx >> 2, part = idx & 3;
            int R = row0 + row;
            int j = node_start + (R >> 9);
            int b = R & (B_ - 1);
            const unsigned short* src = Aw + ((size_t)b * N_ + j) * AK + kt + part * 8;
            cp16(sb + row * (SROW * 2) + part * 16, src);
        }
        // B tile: 512 16B chunks
#pragma unroll
        for (int i = 0; i < 2; ++i) {
            int idx = i * GT_THREADS + t;          // 0..511
            int row = idx >> 2, part = idx & 3;
            const unsigned short* src = Bw + (size_t)(col0 + row) * WK + kt + part * 8;
            cp16(sb + TILE_B + row * (SROW * 2) + part * 16, src);
        }
    };

    const int lr = lid & 15, lc = (lid >> 4) * 8;
    auto compute_stage = [&](int slot) {
        uint32_t sA = sbase + slot * STAGE_B;
        uint32_t sB = sA + TILE_B;
#pragma unroll
        for (int ks = 0; ks < 32; ks += 16) {
            uint32_t a_f[4][4];
#pragma unroll
            for (int mt = 0; mt < 4; ++mt) {
                uint32_t ad = sA + ((wm + mt * 16 + lr) * SROW + ks + lc) * 2;
                ldsm4(a_f[mt], ad);
            }
            uint32_t b_f[2][4];
#pragma unroll
            for (int nh = 0; nh < 2; ++nh) {
                uint32_t bd = sB + ((wn + nh * 16 + lr) * SROW + ks + lc) * 2;
                ldsm4(b_f[nh], bd);
            }
#pragma unroll
            for (int mt = 0; mt < 4; ++mt)
#pragma unroll
                for (int nt = 0; nt < 4; ++nt) {
                    uint32_t b0 = b_f[nt >> 1][nt & 1], b1 = b_f[nt >> 1][(nt & 1) + 2];
                    mma16816(acc[mt][nt], a_f[mt], b0, b1);
                }
        }
    };

    load_stage(0, 0);
    CP_COMMIT();
#pragma unroll 1
    for (int it = 0; it < 10; ++it) {
        if (it + 1 < 10) {
            load_stage((it + 1) & 1, (it + 1) * 32);
            CP_COMMIT();
            CP_WAIT(1);
        } else {
            CP_WAIT(0);
        }
        __syncthreads();
        compute_stage(it & 1);
        __syncthreads();
    }

    // ---- epilogue: fp16 half2 stores (cc always even) ----
    const int g = lid >> 2, i4 = lid & 3;
#pragma unroll
    for (int mt = 0; mt < 4; ++mt) {
        int r0 = row0 + wm + mt * 16 + g;
#pragma unroll
        for (int nt = 0; nt < 4; ++nt) {
            int cc = col0 + wn + nt * 8 + i4 * 2;
            float b0v = 0.0f, b1v = 0.0f;
            if (bias) { b0v = bias[cc]; b1v = bias[cc + 1]; }
            *(uint32_t*)(Out + (size_t)r0 * ostride + cc) =
                pack_f16_2(acc[mt][nt][0] + b0v, acc[mt][nt][1] + b1v);
            *(uint32_t*)(Out + (size_t)(r0 + 8) * ostride + cc) =
                pack_f16_2(acc[mt][nt][2] + b0v, acc[mt][nt][3] + b1v);
        }
    }
}

// Z GEMM: blockIdx.x = col tile (L2 A-reuse), blockIdx.y = row tile
__global__ __launch_bounds__(GT_THREADS) void gemm_m(
    const unsigned short* __restrict__ Aw, int node_start,
    const unsigned short* __restrict__ Bw,
    const float* __restrict__ bias, unsigned short* __restrict__ Out, int ostride)
{
    extern __shared__ char dsm[];
    gemm_tile_body(smem_u32(dsm), threadIdx.x,
                   blockIdx.y * 128, blockIdx.x * 128,
                   Aw, node_start, Bw, bias, Out, ostride);
}

// Merged two-job GEMM (one launch per tree level): flat grid, job0 = Piou, job1 = Pf.
__global__ __launch_bounds__(GT_THREADS) void gemm2_k(
    const unsigned short* __restrict__ A0, int ns0, const unsigned short* __restrict__ B0,
    unsigned short* __restrict__ O0, int ostride0, int nct0, int tiles0,
    const unsigned short* __restrict__ A1, int ns1, const unsigned short* __restrict__ B1,
    unsigned short* __restrict__ O1, int ostride1, int nct1)
{
    extern __shared__ char dsm[];
    int id = blockIdx.x;
    if (id < tiles0) {
        int row0 = (id / nct0) * 128, col0 = (id % nct0) * 128;
        gemm_tile_body(smem_u32(dsm), threadIdx.x, row0, col0,
                       A0, ns0, B0, nullptr, O0, ostride0);
    } else {
        id -= tiles0;
        int row0 = (id / nct1) * 128, col0 = (id % nct1) * 128;
        gemm_tile_body(smem_u32(dsm), threadIdx.x, row0, col0,
                       A1, ns1, B1, nullptr, O1, ostride1);
    }
}

// ---------------- fused elementwise (half2 loads, sibling pairs, inline hsum) ----------------

__device__ __forceinline__ float2 leaf_node2(int j, int b, int d, float* __restrict__ out) {
    size_t zr = ((size_t)j * B_ + b) * FDP + d;
    float2 zi = ldh2(g_Z + zr);
    float2 zo = ldh2(g_Z + zr + D_);
    float2 zu = ldh2(g_Z + zr + 2 * D_);
    float2 c, h;
    c.x = sigm(zi.x) * tanhf(zu.x);
    c.y = sigm(zi.y) * tanhf(zu.y);
    h.x = sigm(zo.x) * tanhf(c.x);
    h.y = sigm(zo.y) * tanhf(c.y);
    *(float2*)(g_C + ((size_t)j * B_ + b) * D_ + d) = c;
    size_t ro = (size_t)b * N_ + j;
    *(float2*)(out + ro * D_ + d) = h;
    *(uint32_t*)(g_h16 + ro * AK + d) = pack_f16_2(h.x, h.y);
    return h;
}

__device__ __forceinline__ float2 comb_node2(int j, int b, int d, float* __restrict__ out) {
    size_t zr = ((size_t)j * B_ + b) * FDP + d;
    size_t pj = ((size_t)j * B_ + b) * PIOU_N + d;
    int a = 2 * j + 1, a2 = 2 * j + 2;
    float2 zi = ldh2(g_Z + zr);
    float2 zo = ldh2(g_Z + zr + D_);
    float2 zu = ldh2(g_Z + zr + 2 * D_);
    float2 zf = ldh2(g_Z + zr + 3 * D_);
    float2 pi = ldh2(g_Piou + pj);
    float2 po = ldh2(g_Piou + pj + D_);
    float2 pu = ldh2(g_Piou + pj + 2 * D_);
    float2 fa2 = ldh2(g_Pf + ((size_t)a  * B_ + b) * PF_N + d);
    float2 fb2 = ldh2(g_Pf + ((size_t)a2 * B_ + b) * PF_N + d);
    float2 ca = *(const float2*)(g_C + ((size_t)a  * B_ + b) * D_ + d);
    float2 cb = *(const float2*)(g_C + ((size_t)a2 * B_ + b) * D_ + d);
    float2 c, h;
    {
        float ii = sigm(zi.x + pi.x), oo = sigm(zo.x + po.x), uu = tanhf(zu.x + pu.x);
        float fa = sigm(fa2.x + zf.x), fb = sigm(fb2.x + zf.x);
        c.x = ii * uu + fa * ca.x + fb * cb.x;
        h.x = oo * tanhf(c.x);
    }
    {
        float ii = sigm(zi.y + pi.y), oo = sigm(zo.y + po.y), uu = tanhf(zu.y + pu.y);
        float fa = sigm(fa2.y + zf.y), fb = sigm(fb2.y + zf.y);
        c.y = ii * uu + fa * ca.y + fb * cb.y;
        h.y = oo * tanhf(c.y);
    }
    *(float2*)(g_C + ((size_t)j * B_ + b) * D_ + d) = c;
    size_t ro = (size_t)b * N_ + j;
    *(float2*)(out + ro * D_ + d) = h;
    *(uint32_t*)(g_h16 + ro * AK + d) = pack_f16_2(h.x, h.y);
    return h;
}

__device__ __forceinline__ void store_hs2(int jp, int b, int d, float2 h1, float2 h2) {
    float sx = h1.x + h2.x, sy = h1.y + h2.y;
    size_t ro = (size_t)b * N_ + jp;
    *(uint32_t*)(g_hs16 + ro * AK + d) = pack_f16_2(sx, sy);
}

#define D2 (D_ / 2)   // 150
__global__ void leaf_fused_k(float* __restrict__ out) {
    int idx = blockIdx.x * blockDim.x + threadIdx.x;
    const int total = 32 * B_ * D2;
    if (idx >= total) return;
    int d  = (idx % D2) * 2;
    int rb = idx / D2;
    int b  = rb % B_;
    int jp = 31 + rb / B_;                 // level-5 parent
    float2 h1 = leaf_node2(2 * jp + 1, b, d, out);
    float2 h2 = leaf_node2(2 * jp + 2, b, d, out);
    store_hs2(jp, b, d, h1, h2);
}

__global__ void comb_fused_k(int pstart, int npar, float* __restrict__ out) {
    int idx = blockIdx.x * blockDim.x + threadIdx.x;
    int total = npar * B_ * D2;
    if (idx >= total) return;
    int d  = (idx % D2) * 2;
    int rb = idx / D2;
    int b  = rb % B_;
    int jp = pstart + rb / B_;             // level pl-1 parent
    float2 h1 = comb_node2(2 * jp + 1, b, d, out);
    float2 h2 = comb_node2(2 * jp + 2, b, d, out);
    store_hs2(jp, b, d, h1, h2);
}

__global__ void comb_root_k(float* __restrict__ out) {
    int idx = blockIdx.x * blockDim.x + threadIdx.x;
    const int total = B_ * D2;
    if (idx >= total) return;
    int d = (idx % D2) * 2;
    int b = idx / D2;
    comb_node2(0, b, d, out);
}

extern "C" void kernel_launch(void* const* d_in, const int* in_sizes, int n_in,
                              void* d_out, int out_size) {
    const float* x     = (const float*)d_in[0];
    const float* Wioux = (const float*)d_in[1];
    const float* bioux = (const float*)d_in[2];
    const float* Wiouh = (const float*)d_in[3];
    const float* biouh = (const float*)d_in[4];
    const float* Wfx   = (const float*)d_in[5];
    const float* bfx   = (const float*)d_in[6];
    const float* Wfh   = (const float*)d_in[7];
    const float* bfh   = (const float*)d_in[8];
    float* out = (float*)d_out;

    float *bcp;
    unsigned short *Zp, *Piou, *Pf, *x16, *h16, *hs16, *wc, *wi2, *wfh2;
    cudaGetSymbolAddress((void**)&Zp,   g_Z);
    cudaGetSymbolAddress((void**)&Piou, g_Piou);
    cudaGetSymbolAddress((void**)&Pf,   g_Pf);
    cudaGetSymbolAddress((void**)&bcp,  g_bc);
    cudaGetSymbolAddress((void**)&x16,  g_x16);
    cudaGetSymbolAddress((void**)&h16,  g_h16);
    cudaGetSymbolAddress((void**)&hs16, g_hs16);
    cudaGetSymbolAddress((void**)&wc,   g_WtC);
    cudaGetSymbolAddress((void**)&wi2,  g_Wiou2);
    cudaGetSymbolAddress((void**)&wfh2, g_Wfh2);

    cudaFuncSetAttribute(gemm_m,  cudaFuncAttributeMaxDynamicSharedMemorySize, SMEM_DYN);
    cudaFuncSetAttribute(gemm2_k, cudaFuncAttributeMaxDynamicSharedMemorySize, SMEM_DYN);

    // 1. pack weights (transpose + fp16) + combined bias
    pack_k<<<(FDP * WK + 255) / 256, 256>>>(Wioux, bioux, Wiouh, biouh, Wfx, bfx, Wfh, bfh);

    // 2. convert x to fp16
    xconv_k<<<(N_ * B_ * (AK / 2) + 255) / 256, 256>>>(x);

    // 3. Z = x @ [Wioux|Wfx] + bias, all nodes  (M = 65024, N = 1280)
    {
        dim3 grid(FDP / 128, (N_ * B_) / 128);
        gemm_m<<<grid, GT_THREADS, SMEM_DYN>>>(x16, 0, wc, bcp, Zp, FDP);
    }

    // 4. leaves (nodes 63..126) + hs for level-5 parents, fused
    leaf_fused_k<<<(32 * B_ * D2 + 255) / 256, 256>>>(out);

    // 5. levels pl = 5 .. 1: merged GEMM, then fused comb (+ hs for pl-1)
    for (int pl = 5; pl >= 1; --pl) {
        int ps = (1 << pl) - 1, np = 1 << pl;             // parent start/count (level pl)
        int cs = (1 << (pl + 1)) - 1, nc = 1 << (pl + 1); // child start/count  (level pl+1)

        int tiles0 = (np * 4) * (PIOU_N / 128);
        int tiles1 = (nc * 4) * (PF_N / 128);
        gemm2_k<<<tiles0 + tiles1, GT_THREADS, SMEM_DYN>>>(
            hs16, ps, wi2, Piou + (size_t)ps * B_ * PIOU_N, PIOU_N, PIOU_N / 128, tiles0,
            h16,  cs, wfh2, Pf  + (size_t)cs * B_ * PF_N,  PF_N,  PF_N / 128);

        int pps = (1 << (pl - 1)) - 1, npp = 1 << (pl - 1);
        comb_fused_k<<<(npp * B_ * D2 + 255) / 256, 256>>>(pps, npp, out);
    }

    // 6. root: gemm for node 0 (Piou) + children 1,2 (Pf), then root comb
    {
        int tiles0 = 4 * (PIOU_N / 128);   // 32
        int tiles1 = 8 * (PF_N / 128);     // 24
        gemm2_k<<<tiles0 + tiles1, GT_THREADS, SMEM_DYN>>>(
            hs16, 0, wi2, Piou, PIOU_N, PIOU_N / 128, tiles0,
            h16,  1, wfh2, Pf + (size_t)1 * B_ * PF_N, PF_N, PF_N / 128);
        comb_root_k<<<(B_ * D2 + 255) / 256, 256>>>(out);
    }
    (void)in_sizes; (void)n_in; (void)out_size;
}